// round 2
// baseline (speedup 1.0000x reference)
#include <cuda_runtime.h>
#include <math.h>

// ---------------- problem constants ----------------
constexpr int BATCH   = 64;
constexpr int NTOK    = 197;
constexpr int DIM     = 768;
constexpr int HEADS   = 12;
constexpr int DHEAD   = 64;
constexpr int INNER   = HEADS * DHEAD;      // 768
constexpr int MROWS   = BATCH * NTOK;       // 12608
constexpr int QKVCOLS = 3 * INNER;          // 2304
constexpr float MASK_FILL = -987654321.0f;

// padded token count / padded shared row for attention
constexpr int NPAD = 224;   // multiple of 32 covering 197
constexpr int LD   = 65;    // 64 + 1 pad -> conflict-free strided access

// ---------------- scratch (device globals; no allocs allowed) ----------------
__device__ float g_qkv[(size_t)MROWS * QKVCOLS];               // x @ w_qkv
__device__ float g_q[(size_t)BATCH * HEADS * NTOK * DHEAD];    // [bh][n][dh], scaled + rotary
__device__ float g_k[(size_t)BATCH * HEADS * NTOK * DHEAD];    // [bh][n][dh], rotary
__device__ float g_v[(size_t)BATCH * HEADS * NTOK * DHEAD];    // [bh][n][dh]
__device__ float g_att[(size_t)MROWS * INNER];                 // [b*n][h*dh]

// ---------------- 128x128x8 register-blocked SGEMM ----------------
// C[M,N] = A[M,K] @ B[K,N] (+ bias[N] if bias != nullptr)
// Requires: N % 128 == 0, K % 8 == 0. M guarded.
__global__ __launch_bounds__(256) void sgemm_kernel(
    const float* __restrict__ A, const float* __restrict__ Bm,
    const float* __restrict__ bias, float* __restrict__ C,
    int M, int N, int K)
{
    __shared__ float As[8][128];
    __shared__ float Bs[8][128];

    const int tid  = threadIdx.x;
    const int tr   = tid >> 4;          // 0..15
    const int tc   = tid & 15;          // 0..15
    const int rowA = tid >> 1;          // 0..127
    const int colA = (tid & 1) << 2;    // 0 or 4
    const int rowB = tid >> 5;          // 0..7
    const int colB = (tid & 31) << 2;   // 0..124
    const int mBase = blockIdx.y * 128;
    const int nBase = blockIdx.x * 128;

    float acc[8][8];
    #pragma unroll
    for (int i = 0; i < 8; i++)
        #pragma unroll
        for (int j = 0; j < 8; j++) acc[i][j] = 0.f;

    for (int k0 = 0; k0 < K; k0 += 8) {
        // A tile (transposed into As[k][m])
        int m = mBase + rowA;
        float4 a4 = make_float4(0.f, 0.f, 0.f, 0.f);
        if (m < M) a4 = *(const float4*)(A + (size_t)m * K + k0 + colA);
        As[colA + 0][rowA] = a4.x;
        As[colA + 1][rowA] = a4.y;
        As[colA + 2][rowA] = a4.z;
        As[colA + 3][rowA] = a4.w;
        // B tile
        *(float4*)&Bs[rowB][colB] =
            *(const float4*)(Bm + (size_t)(k0 + rowB) * N + nBase + colB);
        __syncthreads();

        #pragma unroll
        for (int k = 0; k < 8; k++) {
            float regM[8], regN[8];
            *(float4*)&regM[0] = *(float4*)&As[k][tr * 8];
            *(float4*)&regM[4] = *(float4*)&As[k][tr * 8 + 4];
            *(float4*)&regN[0] = *(float4*)&Bs[k][tc * 8];
            *(float4*)&regN[4] = *(float4*)&Bs[k][tc * 8 + 4];
            #pragma unroll
            for (int i = 0; i < 8; i++)
                #pragma unroll
                for (int j = 0; j < 8; j++)
                    acc[i][j] += regM[i] * regN[j];
        }
        __syncthreads();
    }

    #pragma unroll
    for (int i = 0; i < 8; i++) {
        int m = mBase + tr * 8 + i;
        if (m >= M) continue;
        #pragma unroll
        for (int j4 = 0; j4 < 8; j4 += 4) {
            int n = nBase + tc * 8 + j4;
            float4 c4;
            c4.x = acc[i][j4 + 0];
            c4.y = acc[i][j4 + 1];
            c4.z = acc[i][j4 + 2];
            c4.w = acc[i][j4 + 3];
            if (bias) {
                c4.x += bias[n + 0];
                c4.y += bias[n + 1];
                c4.z += bias[n + 2];
                c4.w += bias[n + 3];
            }
            *(float4*)(C + (size_t)m * N + n) = c4;
        }
    }
}

// ---------------- rotary + scale + scatter to [bh][n][dh] ----------------
// One thread per (token m, pair p) with p in [0, 384): h = p/32, t = p%32.
// sin[i,2t]=sin[i,2t+1]=pos_emb[i,t]; cos pair = pos_emb[i,32+t].
// q' = q*cos + rotate_every_two(q)*sin, pre-multiplied by scale[h].
__global__ __launch_bounds__(256) void rotary_scatter_kernel(
    const float* __restrict__ qkv, const float* __restrict__ pos_emb,
    const float* __restrict__ scale,
    float* __restrict__ q, float* __restrict__ k, float* __restrict__ v)
{
    int idx = blockIdx.x * blockDim.x + threadIdx.x;
    if (idx >= MROWS * 384) return;
    int m = idx / 384;
    int p = idx - m * 384;
    int h = p >> 5;
    int t = p & 31;
    int i = m % NTOK;
    int b = m / NTOK;

    float sn = pos_emb[i * DHEAD + t];
    float cs = pos_emb[i * DHEAD + 32 + t];

    const float* row = qkv + (size_t)m * QKVCOLS;
    int col = h * DHEAD + 2 * t;
    float q0 = row[col],           q1 = row[col + 1];
    float k0 = row[INNER + col],   k1 = row[INNER + col + 1];
    float v0 = row[2*INNER + col], v1 = row[2*INNER + col + 1];
    float sc = scale[h];

    size_t dst = (((size_t)(b * HEADS + h)) * NTOK + i) * DHEAD + 2 * t;
    q[dst]     = (q0 * cs - q1 * sn) * sc;
    q[dst + 1] = (q1 * cs + q0 * sn) * sc;
    k[dst]     = k0 * cs - k1 * sn;
    k[dst + 1] = k1 * cs + k0 * sn;
    v[dst]     = v0;
    v[dst + 1] = v1;
}

// ---------------- attention: one block per (b, h) ----------------
// smem: Ks[NPAD][LD], Vs[NPAD][LD], P[8 warps][4 rows][NPAD]
// Each warp processes 4 query rows at a time (register-blocked), softmax
// over 197 keys (diag masked), then P @ V accumulation, writes [b*n][h*dh].
constexpr int ATT_SMEM_FLOATS = NPAD * LD * 2 + 8 * 4 * NPAD;
constexpr int ATT_SMEM_BYTES  = ATT_SMEM_FLOATS * 4;   // 145152

__global__ __launch_bounds__(256) void attention_kernel(
    const float* __restrict__ gq, const float* __restrict__ gk,
    const float* __restrict__ gv, float* __restrict__ gout)
{
    extern __shared__ float sm[];
    float* Ks = sm;
    float* Vs = sm + NPAD * LD;
    float* P  = sm + 2 * NPAD * LD;

    const int bh   = blockIdx.x;
    const int b    = bh / HEADS;
    const int h    = bh - b * HEADS;
    const int tid  = threadIdx.x;
    const int w    = tid >> 5;
    const int lane = tid & 31;
    const size_t base = (size_t)bh * NTOK * DHEAD;

    // cooperative K/V load (zero-fill padding rows)
    for (int idx = tid; idx < NPAD * DHEAD; idx += 256) {
        int j = idx >> 6;
        int d = idx & 63;
        float kv = 0.f, vv = 0.f;
        if (j < NTOK) { kv = gk[base + idx]; vv = gv[base + idx]; }
        Ks[j * LD + d] = kv;
        Vs[j * LD + d] = vv;
    }
    __syncthreads();

    float* Pw = P + w * 4 * NPAD;

    // per-lane key-row pointers (j = jj*32 + lane)
    const float* kr[7];
    #pragma unroll
    for (int jj = 0; jj < 7; jj++) kr[jj] = Ks + (jj * 32 + lane) * LD;

    for (int i0 = w * 4; i0 < NTOK; i0 += 32) {
        // load 4 query rows: lane holds q[r][lane], q[r][lane+32]
        float qlo[4], qhi[4];
        #pragma unroll
        for (int r = 0; r < 4; r++) {
            int i = i0 + r;
            if (i < NTOK) {
                qlo[r] = gq[base + (size_t)i * DHEAD + lane];
                qhi[r] = gq[base + (size_t)i * DHEAD + 32 + lane];
            } else { qlo[r] = 0.f; qhi[r] = 0.f; }
        }

        float s[4][7];
        #pragma unroll
        for (int r = 0; r < 4; r++)
            #pragma unroll
            for (int jj = 0; jj < 7; jj++) s[r][jj] = 0.f;

        // dots, d = 0..31 (qlo)
        #pragma unroll 4
        for (int d = 0; d < 32; d++) {
            float q0 = __shfl_sync(0xffffffffu, qlo[0], d);
            float q1 = __shfl_sync(0xffffffffu, qlo[1], d);
            float q2 = __shfl_sync(0xffffffffu, qlo[2], d);
            float q3 = __shfl_sync(0xffffffffu, qlo[3], d);
            #pragma unroll
            for (int jj = 0; jj < 7; jj++) {
                float kv = kr[jj][d];
                s[0][jj] += q0 * kv;
                s[1][jj] += q1 * kv;
                s[2][jj] += q2 * kv;
                s[3][jj] += q3 * kv;
            }
        }
        // dots, d = 32..63 (qhi)
        #pragma unroll 4
        for (int d = 0; d < 32; d++) {
            float q0 = __shfl_sync(0xffffffffu, qhi[0], d);
            float q1 = __shfl_sync(0xffffffffu, qhi[1], d);
            float q2 = __shfl_sync(0xffffffffu, qhi[2], d);
            float q3 = __shfl_sync(0xffffffffu, qhi[3], d);
            #pragma unroll
            for (int jj = 0; jj < 7; jj++) {
                float kv = kr[jj][32 + d];
                s[0][jj] += q0 * kv;
                s[1][jj] += q1 * kv;
                s[2][jj] += q2 * kv;
                s[3][jj] += q3 * kv;
            }
        }

        // mask + softmax per row; store unnormalized p to shared
        float invr[4];
        #pragma unroll
        for (int r = 0; r < 4; r++) {
            int i = i0 + r;
            float sv[7];
            float mx = -INFINITY;
            #pragma unroll
            for (int jj = 0; jj < 7; jj++) {
                int j = jj * 32 + lane;
                float val = s[r][jj];
                if (j == i)    val = MASK_FILL;
                if (j >= NTOK) val = -INFINITY;
                sv[jj] = val;
                mx = fmaxf(mx, val);
            }
            #pragma unroll
            for (int off = 16; off > 0; off >>= 1)
                mx = fmaxf(mx, __shfl_xor_sync(0xffffffffu, mx, off));
            float sum = 0.f;
            #pragma unroll
            for (int jj = 0; jj < 7; jj++) {
                float pv = __expf(sv[jj] - mx);
                sum += pv;
                Pw[r * NPAD + jj * 32 + lane] = pv;
            }
            #pragma unroll
            for (int off = 16; off > 0; off >>= 1)
                sum += __shfl_xor_sync(0xffffffffu, sum, off);
            invr[r] = 1.f / sum;
        }
        __syncwarp();

        // out = P @ V  (lane covers d = lane, lane+32; reuse Vs across 4 rows)
        float olo[4] = {0.f, 0.f, 0.f, 0.f};
        float ohi[4] = {0.f, 0.f, 0.f, 0.f};
        for (int j = 0; j < NTOK; j++) {
            float vlo = Vs[j * LD + lane];
            float vhi = Vs[j * LD + 32 + lane];
            #pragma unroll
            for (int r = 0; r < 4; r++) {
                float pv = Pw[r * NPAD + j];
                olo[r] += pv * vlo;
                ohi[r] += pv * vhi;
            }
        }
        #pragma unroll
        for (int r = 0; r < 4; r++) {
            int i = i0 + r;
            if (i < NTOK) {
                size_t o = ((size_t)(b * NTOK + i)) * INNER + h * DHEAD;
                gout[o + lane]      = olo[r] * invr[r];
                gout[o + 32 + lane] = ohi[r] * invr[r];
            }
        }
        __syncwarp();
    }
}

// ---------------- launch ----------------
extern "C" void kernel_launch(void* const* d_in, const int* in_sizes, int n_in,
                              void* d_out, int out_size)
{
    const float* x       = (const float*)d_in[0];
    const float* pos_emb = (const float*)d_in[1];
    const float* w_qkv   = (const float*)d_in[2];
    const float* scale   = (const float*)d_in[3];
    const float* w_out   = (const float*)d_in[4];
    const float* b_out   = (const float*)d_in[5];
    float* out = (float*)d_out;

    float *qkv, *q, *k, *v, *att;
    cudaGetSymbolAddress((void**)&qkv, g_qkv);
    cudaGetSymbolAddress((void**)&q,   g_q);
    cudaGetSymbolAddress((void**)&k,   g_k);
    cudaGetSymbolAddress((void**)&v,   g_v);
    cudaGetSymbolAddress((void**)&att, g_att);

    cudaFuncSetAttribute(attention_kernel,
                         cudaFuncAttributeMaxDynamicSharedMemorySize,
                         ATT_SMEM_BYTES);

    // 1) qkv = x @ w_qkv
    {
        dim3 grid(QKVCOLS / 128, (MROWS + 127) / 128);
        sgemm_kernel<<<grid, 256>>>(x, w_qkv, nullptr, qkv, MROWS, QKVCOLS, DIM);
    }
    // 2) rotary + scale + scatter
    {
        int total = MROWS * 384;
        rotary_scatter_kernel<<<(total + 255) / 256, 256>>>(qkv, pos_emb, scale, q, k, v);
    }
    // 3) attention
    attention_kernel<<<BATCH * HEADS, 256, ATT_SMEM_BYTES>>>(q, k, v, att);
    // 4) out = att @ w_out + b_out
    {
        dim3 grid(DIM / 128, (MROWS + 127) / 128);
        sgemm_kernel<<<grid, 256>>>(att, w_out, b_out, out, MROWS, DIM, INNER);
    }
}

// round 4
// speedup vs baseline: 1.5136x; 1.5136x over previous
#include <cuda_runtime.h>
#include <cuda_bf16.h>
#include <cstdint>
#include <math.h>

// ---------------- problem constants ----------------
constexpr int BATCH   = 64;
constexpr int NTOK    = 197;
constexpr int DIM     = 768;
constexpr int HEADS   = 12;
constexpr int DHEAD   = 64;
constexpr int INNER   = HEADS * DHEAD;      // 768
constexpr int MROWS   = BATCH * NTOK;       // 12608
constexpr int QKVCOLS = 3 * INNER;          // 2304
constexpr float MASK_FILL = -987654321.0f;

constexpr int NPAD = 224;
constexpr int LD   = 65;

// ---------------- scratch (device globals) ----------------
__device__ float g_qkv[(size_t)MROWS * QKVCOLS];
__device__ float g_q[(size_t)BATCH * HEADS * NTOK * DHEAD];
__device__ float g_k[(size_t)BATCH * HEADS * NTOK * DHEAD];
__device__ float g_v[(size_t)BATCH * HEADS * NTOK * DHEAD];
__device__ float g_att[(size_t)MROWS * INNER];
__device__ float g_wqkvT[(size_t)QKVCOLS * DIM];   // [N=2304, K=768]
__device__ float g_woutT[(size_t)DIM * INNER];     // [N=768,  K=768]

// ---------------- bf16 split helpers ----------------
__device__ __forceinline__ void split2(float x, float y,
                                       uint32_t& hi, uint32_t& lo) {
    __nv_bfloat16 hx = __float2bfloat16_rn(x);
    __nv_bfloat16 hy = __float2bfloat16_rn(y);
    __nv_bfloat162 hp;
    hp.x = hx; hp.y = hy;
    hi = *reinterpret_cast<uint32_t*>(&hp);
    __nv_bfloat162 lp;
    lp.x = __float2bfloat16_rn(x - __bfloat162float(hx));
    lp.y = __float2bfloat16_rn(y - __bfloat162float(hy));
    lo = *reinterpret_cast<uint32_t*>(&lp);
}

__device__ __forceinline__ void mma16816(float* c, const uint32_t* a,
                                         const uint32_t* b) {
    asm volatile(
        "mma.sync.aligned.m16n8k16.row.col.f32.bf16.bf16.f32 "
        "{%0,%1,%2,%3}, {%4,%5,%6,%7}, {%8,%9}, {%0,%1,%2,%3};"
        : "+f"(c[0]), "+f"(c[1]), "+f"(c[2]), "+f"(c[3])
        : "r"(a[0]), "r"(a[1]), "r"(a[2]), "r"(a[3]),
          "r"(b[0]), "r"(b[1]));
}

// ---------------- bf16x3 split GEMM: C[M,N] = A[M,K] @ BT[N,K]^T (+bias) ---
// grid (N/128, ceil(M/128)), 256 threads. Requires N%128==0, K%32==0.
// SMEM row stride: 40 bf16 = 20 b32 (conflict-free fragment loads).
constexpr int KS32 = 20;

__global__ __launch_bounds__(256) void gemm_bf16x3(
    const float* __restrict__ A, const float* __restrict__ BT,
    const float* __restrict__ bias, float* __restrict__ C,
    int M, int N, int K)
{
    __shared__ uint32_t sAh[128 * KS32], sAl[128 * KS32];
    __shared__ uint32_t sBh[128 * KS32], sBl[128 * KS32];

    const int tid  = threadIdx.x;
    const int lane = tid & 31;
    const int wid  = tid >> 5;
    const int g    = lane >> 2;     // groupID
    const int tig  = lane & 3;      // thread-in-group
    const int wm   = wid & 1;       // 2 m-warps
    const int wn   = wid >> 1;      // 4 n-warps
    const int mBase = blockIdx.y * 128;
    const int nBase = blockIdx.x * 128;

    const int row2    = tid >> 1;           // 0..127
    const int colBase = (tid & 1) * 16;     // 0 or 16 (fp32 col within 32-chunk)

    float acc[4][4][4];
    #pragma unroll
    for (int i = 0; i < 4; i++)
        #pragma unroll
        for (int j = 0; j < 4; j++)
            #pragma unroll
            for (int r = 0; r < 4; r++) acc[i][j][r] = 0.f;

    float4 pA[4], pB[4];

    auto ldg = [&](int kc) {
        const int arow = mBase + row2;
        if (arow < M) {
            const float* ap = A + (size_t)arow * K + kc * 32 + colBase;
            #pragma unroll
            for (int p = 0; p < 4; p++) pA[p] = *(const float4*)(ap + p * 4);
        } else {
            #pragma unroll
            for (int p = 0; p < 4; p++) pA[p] = make_float4(0.f, 0.f, 0.f, 0.f);
        }
        const float* bp = BT + (size_t)(nBase + row2) * K + kc * 32 + colBase;
        #pragma unroll
        for (int p = 0; p < 4; p++) pB[p] = *(const float4*)(bp + p * 4);
    };

    auto sts = [&]() {
        const int ib = row2 * KS32 + (tid & 1) * 8;
        #pragma unroll
        for (int p = 0; p < 4; p++) {
            uint32_t h0, l0, h1, l1;
            split2(pA[p].x, pA[p].y, h0, l0);
            split2(pA[p].z, pA[p].w, h1, l1);
            sAh[ib + p * 2]     = h0;
            sAh[ib + p * 2 + 1] = h1;
            sAl[ib + p * 2]     = l0;
            sAl[ib + p * 2 + 1] = l1;
            split2(pB[p].x, pB[p].y, h0, l0);
            split2(pB[p].z, pB[p].w, h1, l1);
            sBh[ib + p * 2]     = h0;
            sBh[ib + p * 2 + 1] = h1;
            sBl[ib + p * 2]     = l0;
            sBl[ib + p * 2 + 1] = l1;
        }
    };

    const int KC = K / 32;
    ldg(0);

    for (int kc = 0; kc < KC; kc++) {
        sts();
        __syncthreads();
        if (kc + 1 < KC) ldg(kc + 1);

        #pragma unroll
        for (int half = 0; half < 2; half++) {
            const int kb = half * 8;
            uint32_t ah[4][4], al[4][4], bh[4][2], bl[4][2];
            #pragma unroll
            for (int i = 0; i < 4; i++) {
                int r0 = (wm * 64 + i * 16 + g) * KS32 + kb + tig;
                ah[i][0] = sAh[r0];
                ah[i][1] = sAh[r0 + 8 * KS32];
                ah[i][2] = sAh[r0 + 4];
                ah[i][3] = sAh[r0 + 8 * KS32 + 4];
                al[i][0] = sAl[r0];
                al[i][1] = sAl[r0 + 8 * KS32];
                al[i][2] = sAl[r0 + 4];
                al[i][3] = sAl[r0 + 8 * KS32 + 4];
            }
            #pragma unroll
            for (int j = 0; j < 4; j++) {
                int rn = (wn * 32 + j * 8 + g) * KS32 + kb + tig;
                bh[j][0] = sBh[rn];
                bh[j][1] = sBh[rn + 4];
                bl[j][0] = sBl[rn];
                bl[j][1] = sBl[rn + 4];
            }
            #pragma unroll
            for (int i = 0; i < 4; i++)
                #pragma unroll
                for (int j = 0; j < 4; j++) {
                    mma16816(acc[i][j], ah[i], bh[j]);   // hi*hi
                    mma16816(acc[i][j], al[i], bh[j]);   // lo*hi
                    mma16816(acc[i][j], ah[i], bl[j]);   // hi*lo
                }
        }
        __syncthreads();
    }

    // epilogue: direct float2 stores per fragment (+bias)
    #pragma unroll
    for (int i = 0; i < 4; i++) {
        int r0 = mBase + wm * 64 + i * 16 + g;
        #pragma unroll
        for (int j = 0; j < 4; j++) {
            int c = nBase + wn * 32 + j * 8 + 2 * tig;
            float b0 = bias ? bias[c]     : 0.f;
            float b1 = bias ? bias[c + 1] : 0.f;
            if (r0 < M) {
                float2 v = make_float2(acc[i][j][0] + b0, acc[i][j][1] + b1);
                *(float2*)(C + (size_t)r0 * N + c) = v;
            }
            if (r0 + 8 < M) {
                float2 v = make_float2(acc[i][j][2] + b0, acc[i][j][3] + b1);
                *(float2*)(C + (size_t)(r0 + 8) * N + c) = v;
            }
        }
    }
}

// ---------------- weight transpose: dst[c][r] = src[r][c] ----------------
__global__ __launch_bounds__(256) void transpose_kernel(
    const float* __restrict__ src, float* __restrict__ dst, int R, int C)
{
    __shared__ float t[32][33];
    int c0 = blockIdx.x * 32, r0 = blockIdx.y * 32;
    int x = threadIdx.x, y = threadIdx.y;     // (32, 8)
    #pragma unroll
    for (int i = 0; i < 32; i += 8)
        t[y + i][x] = src[(size_t)(r0 + y + i) * C + c0 + x];
    __syncthreads();
    #pragma unroll
    for (int i = 0; i < 32; i += 8)
        dst[(size_t)(c0 + y + i) * R + r0 + x] = t[x][y + i];
}

// ---------------- rotary + scale + scatter ----------------
__global__ __launch_bounds__(256) void rotary_scatter_kernel(
    const float* __restrict__ qkv, const float* __restrict__ pos_emb,
    const float* __restrict__ scale,
    float* __restrict__ q, float* __restrict__ k, float* __restrict__ v)
{
    int idx = blockIdx.x * blockDim.x + threadIdx.x;
    if (idx >= MROWS * 384) return;
    int m = idx / 384;
    int p = idx - m * 384;
    int h = p >> 5;
    int t = p & 31;
    int i = m % NTOK;
    int b = m / NTOK;

    float sn = pos_emb[i * DHEAD + t];
    float cs = pos_emb[i * DHEAD + 32 + t];

    const float* row = qkv + (size_t)m * QKVCOLS;
    int col = h * DHEAD + 2 * t;
    float q0 = row[col],             q1 = row[col + 1];
    float k0 = row[INNER + col],     k1 = row[INNER + col + 1];
    float v0 = row[2 * INNER + col], v1 = row[2 * INNER + col + 1];
    float sc = scale[h];

    size_t dst = (((size_t)(b * HEADS + h)) * NTOK + i) * DHEAD + 2 * t;
    q[dst]     = (q0 * cs - q1 * sn) * sc;
    q[dst + 1] = (q1 * cs + q0 * sn) * sc;
    k[dst]     = k0 * cs - k1 * sn;
    k[dst + 1] = k1 * cs + k0 * sn;
    v[dst]     = v0;
    v[dst + 1] = v1;
}

// ---------------- attention: one block per (b, h) ----------------
constexpr int ATT_SMEM_FLOATS = NPAD * LD * 2 + 8 * 4 * NPAD;
constexpr int ATT_SMEM_BYTES  = ATT_SMEM_FLOATS * 4;

__global__ __launch_bounds__(256) void attention_kernel(
    const float* __restrict__ gq, const float* __restrict__ gk,
    const float* __restrict__ gv, float* __restrict__ gout)
{
    extern __shared__ float smatt[];
    float* Ks = smatt;
    float* Vs = smatt + NPAD * LD;
    float* P  = smatt + 2 * NPAD * LD;

    const int bh   = blockIdx.x;
    const int b    = bh / HEADS;
    const int h    = bh - b * HEADS;
    const int tid  = threadIdx.x;
    const int w    = tid >> 5;
    const int lane = tid & 31;
    const size_t base = (size_t)bh * NTOK * DHEAD;

    for (int idx = tid; idx < NPAD * DHEAD; idx += 256) {
        int j = idx >> 6;
        int d = idx & 63;
        float kv = 0.f, vv = 0.f;
        if (j < NTOK) { kv = gk[base + idx]; vv = gv[base + idx]; }
        Ks[j * LD + d] = kv;
        Vs[j * LD + d] = vv;
    }
    __syncthreads();

    float* Pw = P + w * 4 * NPAD;

    const float* kr[7];
    #pragma unroll
    for (int jj = 0; jj < 7; jj++) kr[jj] = Ks + (jj * 32 + lane) * LD;

    for (int i0 = w * 4; i0 < NTOK; i0 += 32) {
        float qlo[4], qhi[4];
        #pragma unroll
        for (int r = 0; r < 4; r++) {
            int i = i0 + r;
            if (i < NTOK) {
                qlo[r] = gq[base + (size_t)i * DHEAD + lane];
                qhi[r] = gq[base + (size_t)i * DHEAD + 32 + lane];
            } else { qlo[r] = 0.f; qhi[r] = 0.f; }
        }

        float s[4][7];
        #pragma unroll
        for (int r = 0; r < 4; r++)
            #pragma unroll
            for (int jj = 0; jj < 7; jj++) s[r][jj] = 0.f;

        #pragma unroll 4
        for (int d = 0; d < 32; d++) {
            float q0 = __shfl_sync(0xffffffffu, qlo[0], d);
            float q1 = __shfl_sync(0xffffffffu, qlo[1], d);
            float q2 = __shfl_sync(0xffffffffu, qlo[2], d);
            float q3 = __shfl_sync(0xffffffffu, qlo[3], d);
            #pragma unroll
            for (int jj = 0; jj < 7; jj++) {
                float kv = kr[jj][d];
                s[0][jj] += q0 * kv;
                s[1][jj] += q1 * kv;
                s[2][jj] += q2 * kv;
                s[3][jj] += q3 * kv;
            }
        }
        #pragma unroll 4
        for (int d = 0; d < 32; d++) {
            float q0 = __shfl_sync(0xffffffffu, qhi[0], d);
            float q1 = __shfl_sync(0xffffffffu, qhi[1], d);
            float q2 = __shfl_sync(0xffffffffu, qhi[2], d);
            float q3 = __shfl_sync(0xffffffffu, qhi[3], d);
            #pragma unroll
            for (int jj = 0; jj < 7; jj++) {
                float kv = kr[jj][32 + d];
                s[0][jj] += q0 * kv;
                s[1][jj] += q1 * kv;
                s[2][jj] += q2 * kv;
                s[3][jj] += q3 * kv;
            }
        }

        float invr[4];
        #pragma unroll
        for (int r = 0; r < 4; r++) {
            int i = i0 + r;
            float sv[7];
            float mx = -INFINITY;
            #pragma unroll
            for (int jj = 0; jj < 7; jj++) {
                int j = jj * 32 + lane;
                float val = s[r][jj];
                if (j == i)    val = MASK_FILL;
                if (j >= NTOK) val = -INFINITY;
                sv[jj] = val;
                mx = fmaxf(mx, val);
            }
            #pragma unroll
            for (int off = 16; off > 0; off >>= 1)
                mx = fmaxf(mx, __shfl_xor_sync(0xffffffffu, mx, off));
            float sum = 0.f;
            #pragma unroll
            for (int jj = 0; jj < 7; jj++) {
                float pv = __expf(sv[jj] - mx);
                sum += pv;
                Pw[r * NPAD + jj * 32 + lane] = pv;
            }
            #pragma unroll
            for (int off = 16; off > 0; off >>= 1)
                sum += __shfl_xor_sync(0xffffffffu, sum, off);
            invr[r] = 1.f / sum;
        }
        __syncwarp();

        float olo[4] = {0.f, 0.f, 0.f, 0.f};
        float ohi[4] = {0.f, 0.f, 0.f, 0.f};
        for (int j = 0; j < NTOK; j++) {
            float vlo = Vs[j * LD + lane];
            float vhi = Vs[j * LD + 32 + lane];
            #pragma unroll
            for (int r = 0; r < 4; r++) {
                float pv = Pw[r * NPAD + j];
                olo[r] += pv * vlo;
                ohi[r] += pv * vhi;
            }
        }
        #pragma unroll
        for (int r = 0; r < 4; r++) {
            int i = i0 + r;
            if (i < NTOK) {
                size_t o = ((size_t)(b * NTOK + i)) * INNER + h * DHEAD;
                gout[o + lane]      = olo[r] * invr[r];
                gout[o + 32 + lane] = ohi[r] * invr[r];
            }
        }
        __syncwarp();
    }
}

// ---------------- launch ----------------
extern "C" void kernel_launch(void* const* d_in, const int* in_sizes, int n_in,
                              void* d_out, int out_size)
{
    const float* x       = (const float*)d_in[0];
    const float* pos_emb = (const float*)d_in[1];
    const float* w_qkv   = (const float*)d_in[2];
    const float* scale   = (const float*)d_in[3];
    const float* w_out   = (const float*)d_in[4];
    const float* b_out   = (const float*)d_in[5];
    float* out = (float*)d_out;

    float *qkv, *q, *k, *v, *att, *wqkvT, *woutT;
    cudaGetSymbolAddress((void**)&qkv,   g_qkv);
    cudaGetSymbolAddress((void**)&q,     g_q);
    cudaGetSymbolAddress((void**)&k,     g_k);
    cudaGetSymbolAddress((void**)&v,     g_v);
    cudaGetSymbolAddress((void**)&att,   g_att);
    cudaGetSymbolAddress((void**)&wqkvT, g_wqkvT);
    cudaGetSymbolAddress((void**)&woutT, g_woutT);

    cudaFuncSetAttribute(attention_kernel,
                         cudaFuncAttributeMaxDynamicSharedMemorySize,
                         ATT_SMEM_BYTES);

    // 0) transpose weights to [N, K] K-major for the MMA B operand
    transpose_kernel<<<dim3(QKVCOLS / 32, DIM / 32), dim3(32, 8)>>>(
        w_qkv, wqkvT, DIM, QKVCOLS);
    transpose_kernel<<<dim3(DIM / 32, INNER / 32), dim3(32, 8)>>>(
        w_out, woutT, INNER, DIM);

    // 1) qkv = x @ w_qkv   (bf16x3 tensor-core)
    gemm_bf16x3<<<dim3(QKVCOLS / 128, (MROWS + 127) / 128), 256>>>(
        x, wqkvT, nullptr, qkv, MROWS, QKVCOLS, DIM);

    // 2) rotary + scale + scatter
    {
        int total = MROWS * 384;
        rotary_scatter_kernel<<<(total + 255) / 256, 256>>>(qkv, pos_emb, scale,
                                                            q, k, v);
    }

    // 3) attention
    attention_kernel<<<BATCH * HEADS, 256, ATT_SMEM_BYTES>>>(q, k, v, att);

    // 4) out = att @ w_out + b_out   (bf16x3 tensor-core)
    gemm_bf16x3<<<dim3(DIM / 128, (MROWS + 127) / 128), 256>>>(
        att, woutT, b_out, out, MROWS, DIM, INNER);
}

// round 7
// speedup vs baseline: 1.5161x; 1.0016x over previous
#include <cuda_runtime.h>
#include <cuda_bf16.h>
#include <cstdint>
#include <math.h>

// ---------------- problem constants ----------------
constexpr int BATCH   = 64;
constexpr int NTOK    = 197;
constexpr int DIM     = 768;
constexpr int HEADS   = 12;
constexpr int DHEAD   = 64;
constexpr int INNER   = HEADS * DHEAD;      // 768
constexpr int MROWS   = BATCH * NTOK;       // 12608
constexpr int QKVCOLS = 3 * INNER;          // 2304
constexpr float MASK_FILL = -987654321.0f;

// ---------------- scratch (device globals) ----------------
__device__ float g_qkv[(size_t)MROWS * QKVCOLS];
__device__ float g_q[(size_t)BATCH * HEADS * NTOK * DHEAD];
__device__ float g_k[(size_t)BATCH * HEADS * NTOK * DHEAD];
__device__ float g_v[(size_t)BATCH * HEADS * NTOK * DHEAD];
__device__ float g_att[(size_t)MROWS * INNER];
__device__ float g_wqkvT[(size_t)QKVCOLS * DIM];   // [N=2304, K=768]
__device__ float g_woutT[(size_t)DIM * INNER];     // [N=768,  K=768]

// ---------------- bf16 split helpers ----------------
__device__ __forceinline__ void split2(float x, float y,
                                       uint32_t& hi, uint32_t& lo) {
    __nv_bfloat16 hx = __float2bfloat16_rn(x);
    __nv_bfloat16 hy = __float2bfloat16_rn(y);
    __nv_bfloat162 hp;
    hp.x = hx; hp.y = hy;
    hi = *reinterpret_cast<uint32_t*>(&hp);
    __nv_bfloat162 lp;
    lp.x = __float2bfloat16_rn(x - __bfloat162float(hx));
    lp.y = __float2bfloat16_rn(y - __bfloat162float(hy));
    lo = *reinterpret_cast<uint32_t*>(&lp);
}

__device__ __forceinline__ void mma16816(float* c, const uint32_t* a,
                                         const uint32_t* b) {
    asm volatile(
        "mma.sync.aligned.m16n8k16.row.col.f32.bf16.bf16.f32 "
        "{%0,%1,%2,%3}, {%4,%5,%6,%7}, {%8,%9}, {%0,%1,%2,%3};"
        : "+f"(c[0]), "+f"(c[1]), "+f"(c[2]), "+f"(c[3])
        : "r"(a[0]), "r"(a[1]), "r"(a[2]), "r"(a[3]),
          "r"(b[0]), "r"(b[1]));
}

__device__ __forceinline__ void ldm_x4(uint32_t* r, uint32_t addr) {
    asm volatile("ldmatrix.sync.aligned.m8n8.x4.shared.b16 {%0,%1,%2,%3}, [%4];"
        : "=r"(r[0]), "=r"(r[1]), "=r"(r[2]), "=r"(r[3]) : "r"(addr));
}

__device__ __forceinline__ void ldm_x4_t(uint32_t* r, uint32_t addr) {
    asm volatile("ldmatrix.sync.aligned.m8n8.x4.trans.shared.b16 {%0,%1,%2,%3}, [%4];"
        : "=r"(r[0]), "=r"(r[1]), "=r"(r[2]), "=r"(r[3]) : "r"(addr));
}

__device__ __forceinline__ uint32_t smem_u32(const void* p) {
    uint32_t a;
    asm("{ .reg .u64 t; cvta.to.shared.u64 t, %1; cvt.u32.u64 %0, t; }"
        : "=r"(a) : "l"(p));
    return a;
}

// ---------------- bf16x3 split GEMM: C[M,N] = A[M,K] @ BT[N,K]^T (+bias) ---
constexpr int KS32 = 20;

__global__ __launch_bounds__(256) void gemm_bf16x3(
    const float* __restrict__ A, const float* __restrict__ BT,
    const float* __restrict__ bias, float* __restrict__ C,
    int M, int N, int K)
{
    __shared__ uint32_t sAh[128 * KS32], sAl[128 * KS32];
    __shared__ uint32_t sBh[128 * KS32], sBl[128 * KS32];

    const int tid  = threadIdx.x;
    const int lane = tid & 31;
    const int wid  = tid >> 5;
    const int g    = lane >> 2;
    const int tig  = lane & 3;
    const int wm   = wid & 1;
    const int wn   = wid >> 1;
    const int mBase = blockIdx.y * 128;
    const int nBase = blockIdx.x * 128;

    const int row2    = tid >> 1;
    const int colBase = (tid & 1) * 16;

    float acc[4][4][4];
    #pragma unroll
    for (int i = 0; i < 4; i++)
        #pragma unroll
        for (int j = 0; j < 4; j++)
            #pragma unroll
            for (int r = 0; r < 4; r++) acc[i][j][r] = 0.f;

    float4 pA[4], pB[4];

    auto ldg = [&](int kc) {
        const int arow = mBase + row2;
        if (arow < M) {
            const float* ap = A + (size_t)arow * K + kc * 32 + colBase;
            #pragma unroll
            for (int p = 0; p < 4; p++) pA[p] = *(const float4*)(ap + p * 4);
        } else {
            #pragma unroll
            for (int p = 0; p < 4; p++) pA[p] = make_float4(0.f, 0.f, 0.f, 0.f);
        }
        const float* bp = BT + (size_t)(nBase + row2) * K + kc * 32 + colBase;
        #pragma unroll
        for (int p = 0; p < 4; p++) pB[p] = *(const float4*)(bp + p * 4);
    };

    auto sts = [&]() {
        const int ib = row2 * KS32 + (tid & 1) * 8;
        #pragma unroll
        for (int p = 0; p < 4; p++) {
            uint32_t h0, l0, h1, l1;
            split2(pA[p].x, pA[p].y, h0, l0);
            split2(pA[p].z, pA[p].w, h1, l1);
            sAh[ib + p * 2]     = h0;
            sAh[ib + p * 2 + 1] = h1;
            sAl[ib + p * 2]     = l0;
            sAl[ib + p * 2 + 1] = l1;
            split2(pB[p].x, pB[p].y, h0, l0);
            split2(pB[p].z, pB[p].w, h1, l1);
            sBh[ib + p * 2]     = h0;
            sBh[ib + p * 2 + 1] = h1;
            sBl[ib + p * 2]     = l0;
            sBl[ib + p * 2 + 1] = l1;
        }
    };

    const int KC = K / 32;
    ldg(0);

    for (int kc = 0; kc < KC; kc++) {
        sts();
        __syncthreads();
        if (kc + 1 < KC) ldg(kc + 1);

        #pragma unroll
        for (int half = 0; half < 2; half++) {
            const int kb = half * 8;
            uint32_t ah[4][4], al[4][4], bh[4][2], bl[4][2];
            #pragma unroll
            for (int i = 0; i < 4; i++) {
                int r0 = (wm * 64 + i * 16 + g) * KS32 + kb + tig;
                ah[i][0] = sAh[r0];
                ah[i][1] = sAh[r0 + 8 * KS32];
                ah[i][2] = sAh[r0 + 4];
                ah[i][3] = sAh[r0 + 8 * KS32 + 4];
                al[i][0] = sAl[r0];
                al[i][1] = sAl[r0 + 8 * KS32];
                al[i][2] = sAl[r0 + 4];
                al[i][3] = sAl[r0 + 8 * KS32 + 4];
            }
            #pragma unroll
            for (int j = 0; j < 4; j++) {
                int rn = (wn * 32 + j * 8 + g) * KS32 + kb + tig;
                bh[j][0] = sBh[rn];
                bh[j][1] = sBh[rn + 4];
                bl[j][0] = sBl[rn];
                bl[j][1] = sBl[rn + 4];
            }
            #pragma unroll
            for (int i = 0; i < 4; i++)
                #pragma unroll
                for (int j = 0; j < 4; j++) {
                    mma16816(acc[i][j], ah[i], bh[j]);
                    mma16816(acc[i][j], al[i], bh[j]);
                    mma16816(acc[i][j], ah[i], bl[j]);
                }
        }
        __syncthreads();
    }

    #pragma unroll
    for (int i = 0; i < 4; i++) {
        int r0 = mBase + wm * 64 + i * 16 + g;
        #pragma unroll
        for (int j = 0; j < 4; j++) {
            int c = nBase + wn * 32 + j * 8 + 2 * tig;
            float b0 = bias ? bias[c]     : 0.f;
            float b1 = bias ? bias[c + 1] : 0.f;
            if (r0 < M) {
                float2 v = make_float2(acc[i][j][0] + b0, acc[i][j][1] + b1);
                *(float2*)(C + (size_t)r0 * N + c) = v;
            }
            if (r0 + 8 < M) {
                float2 v = make_float2(acc[i][j][2] + b0, acc[i][j][3] + b1);
                *(float2*)(C + (size_t)(r0 + 8) * N + c) = v;
            }
        }
    }
}

// ---------------- weight transpose ----------------
__global__ __launch_bounds__(256) void transpose_kernel(
    const float* __restrict__ src, float* __restrict__ dst, int R, int C)
{
    __shared__ float t[32][33];
    int c0 = blockIdx.x * 32, r0 = blockIdx.y * 32;
    int x = threadIdx.x, y = threadIdx.y;
    #pragma unroll
    for (int i = 0; i < 32; i += 8)
        t[y + i][x] = src[(size_t)(r0 + y + i) * C + c0 + x];
    __syncthreads();
    #pragma unroll
    for (int i = 0; i < 32; i += 8)
        dst[(size_t)(c0 + y + i) * R + r0 + x] = t[x][y + i];
}

// ---------------- rotary + scale + scatter ----------------
__global__ __launch_bounds__(256) void rotary_scatter_kernel(
    const float* __restrict__ qkv, const float* __restrict__ pos_emb,
    const float* __restrict__ scale,
    float* __restrict__ q, float* __restrict__ k, float* __restrict__ v)
{
    int idx = blockIdx.x * blockDim.x + threadIdx.x;
    if (idx >= MROWS * 384) return;
    int m = idx / 384;
    int p = idx - m * 384;
    int h = p >> 5;
    int t = p & 31;
    int i = m % NTOK;
    int b = m / NTOK;

    float sn = pos_emb[i * DHEAD + t];
    float cs = pos_emb[i * DHEAD + 32 + t];

    const float* row = qkv + (size_t)m * QKVCOLS;
    int col = h * DHEAD + 2 * t;
    float q0 = row[col],             q1 = row[col + 1];
    float k0 = row[INNER + col],     k1 = row[INNER + col + 1];
    float v0 = row[2 * INNER + col], v1 = row[2 * INNER + col + 1];
    float sc = scale[h];

    size_t dst = (((size_t)(b * HEADS + h)) * NTOK + i) * DHEAD + 2 * t;
    q[dst]     = (q0 * cs - q1 * sn) * sc;
    q[dst + 1] = (q1 * cs + q0 * sn) * sc;
    k[dst]     = k0 * cs - k1 * sn;
    k[dst + 1] = k1 * cs + k0 * sn;
    v[dst]     = v0;
    v[dst + 1] = v1;
}

// ---------------- MMA attention: one block per (b, h) ----------------
// 224 threads = 7 warps; warp w owns query rows [w*32, w*32+32).
// Q: 224 rows, K/V: 256 rows (keys zero-padded), bf16 hi/lo, stride 72 halves.
constexpr int ASTRIDE   = 72;
constexpr int Q_TILE_H  = 224 * ASTRIDE;   // 16128 halves
constexpr int KV_TILE_H = 256 * ASTRIDE;   // 18432 halves
constexpr int ATT_MMA_SMEM = (2 * Q_TILE_H + 4 * KV_TILE_H) * 2;  // 211968 B

__device__ __forceinline__ float maskv(float v, int r, int c) {
    if (c == r)     return MASK_FILL;
    if (c >= NTOK)  return -1e30f;
    return v;
}

__global__ __launch_bounds__(224, 1) void attention_mma(
    const float* __restrict__ gq, const float* __restrict__ gk,
    const float* __restrict__ gv, float* __restrict__ gout)
{
    extern __shared__ __nv_bfloat16 sb[];
    __nv_bfloat16* sQh = sb;
    __nv_bfloat16* sQl = sb + Q_TILE_H;
    __nv_bfloat16* sKh = sb + 2 * Q_TILE_H;
    __nv_bfloat16* sKl = sKh + KV_TILE_H;
    __nv_bfloat16* sVh = sKh + 2 * KV_TILE_H;
    __nv_bfloat16* sVl = sKh + 3 * KV_TILE_H;

    const int bh   = blockIdx.x;
    const int b    = bh / HEADS;
    const int h    = bh - b * HEADS;
    const int tid  = threadIdx.x;
    const int w    = tid >> 5;
    const int lane = tid & 31;
    const int g    = lane >> 2;
    const int tig  = lane & 3;
    const size_t base = (size_t)bh * NTOK * DHEAD;

    // fill smem: K/V rows 0..255, Q rows 0..223 (zero-pad beyond 196)
    for (int idx = tid; idx < 256 * DHEAD; idx += 224) {
        int row = idx >> 6;
        float kv = 0.f, vv = 0.f;
        if (row < NTOK) { kv = gk[base + idx]; vv = gv[base + idx]; }
        int o = row * ASTRIDE + (idx & 63);
        __nv_bfloat16 t;
        t = __float2bfloat16_rn(kv);
        sKh[o] = t;
        sKl[o] = __float2bfloat16_rn(kv - __bfloat162float(t));
        t = __float2bfloat16_rn(vv);
        sVh[o] = t;
        sVl[o] = __float2bfloat16_rn(vv - __bfloat162float(t));
        if (row < 224) {
            float qv = (row < NTOK) ? gq[base + idx] : 0.f;
            t = __float2bfloat16_rn(qv);
            sQh[o] = t;
            sQl[o] = __float2bfloat16_rn(qv - __bfloat162float(t));
        }
    }
    __syncthreads();

    const uint32_t aQh = smem_u32(sQh), aQl = smem_u32(sQl);
    const uint32_t aKh = smem_u32(sKh), aKl = smem_u32(sKl);
    const uint32_t aVh = smem_u32(sVh), aVl = smem_u32(sVl);

    // ldmatrix per-lane offsets
    const int qRO = (lane & 7) + ((lane & 8)  ? 8 : 0);   // A-frag / V-trans rows
    const int qCO = (lane & 16) ? 8 : 0;
    const int kRO = (lane & 7) + ((lane & 16) ? 8 : 0);   // B-frag rows
    const int kCO = (lane & 8)  ? 8 : 0;
    const int i0  = w * 32;

    float out[2][8][4];
    #pragma unroll
    for (int it = 0; it < 2; it++)
        #pragma unroll
        for (int jn = 0; jn < 8; jn++)
            #pragma unroll
            for (int r = 0; r < 4; r++) out[it][jn][r] = 0.f;

    float mrow[2][2] = {{-INFINITY, -INFINITY}, {-INFINITY, -INFINITY}};
    float rsum[2][2] = {{0.f, 0.f}, {0.f, 0.f}};

    for (int c = 0; c < 4; c++) {
        const int jc = c * 64;
        float s[2][8][4];
        #pragma unroll
        for (int it = 0; it < 2; it++)
            #pragma unroll
            for (int jn = 0; jn < 8; jn++)
                #pragma unroll
                for (int r = 0; r < 4; r++) s[it][jn][r] = 0.f;

        // ---- S = Q @ K^T (3-term bf16 split) ----
        #pragma unroll
        for (int kk = 0; kk < 4; kk++) {
            uint32_t qh[2][4], ql[2][4];
            #pragma unroll
            for (int it = 0; it < 2; it++) {
                uint32_t off = (uint32_t)((i0 + it * 16 + qRO) * ASTRIDE
                                          + kk * 16 + qCO) * 2;
                ldm_x4(qh[it], aQh + off);
                ldm_x4(ql[it], aQl + off);
            }
            #pragma unroll
            for (int np = 0; np < 4; np++) {
                uint32_t khf[4], klf[4];
                uint32_t off = (uint32_t)((jc + np * 16 + kRO) * ASTRIDE
                                          + kk * 16 + kCO) * 2;
                ldm_x4(khf, aKh + off);
                ldm_x4(klf, aKl + off);
                #pragma unroll
                for (int it = 0; it < 2; it++) {
                    mma16816(s[it][2 * np],     qh[it], khf);
                    mma16816(s[it][2 * np],     ql[it], khf);
                    mma16816(s[it][2 * np],     qh[it], klf);
                    mma16816(s[it][2 * np + 1], qh[it], khf + 2);
                    mma16816(s[it][2 * np + 1], ql[it], khf + 2);
                    mma16816(s[it][2 * np + 1], qh[it], klf + 2);
                }
            }
        }

        // ---- mask + online softmax ----
        float cm[2][2] = {{-INFINITY, -INFINITY}, {-INFINITY, -INFINITY}};
        #pragma unroll
        for (int it = 0; it < 2; it++) {
            int r0 = i0 + it * 16 + g;
            int r1 = r0 + 8;
            #pragma unroll
            for (int jn = 0; jn < 8; jn++) {
                int cb = jc + jn * 8 + 2 * tig;
                float* sv = s[it][jn];
                sv[0] = maskv(sv[0], r0, cb);
                sv[1] = maskv(sv[1], r0, cb + 1);
                sv[2] = maskv(sv[2], r1, cb);
                sv[3] = maskv(sv[3], r1, cb + 1);
                cm[it][0] = fmaxf(cm[it][0], fmaxf(sv[0], sv[1]));
                cm[it][1] = fmaxf(cm[it][1], fmaxf(sv[2], sv[3]));
            }
        }
        #pragma unroll
        for (int it = 0; it < 2; it++)
            #pragma unroll
            for (int hf = 0; hf < 2; hf++) {
                float v = cm[it][hf];
                v = fmaxf(v, __shfl_xor_sync(0xffffffffu, v, 1));
                v = fmaxf(v, __shfl_xor_sync(0xffffffffu, v, 2));
                float mnew = fmaxf(mrow[it][hf], v);
                float sc = __expf(mrow[it][hf] - mnew);
                mrow[it][hf] = mnew;
                rsum[it][hf] *= sc;
                #pragma unroll
                for (int jn = 0; jn < 8; jn++) {
                    out[it][jn][hf * 2]     *= sc;
                    out[it][jn][hf * 2 + 1] *= sc;
                }
            }

        uint32_t pfh[2][4][4], pfl[2][4][4];
        #pragma unroll
        for (int it = 0; it < 2; it++) {
            float ls0 = 0.f, ls1 = 0.f;
            #pragma unroll
            for (int jn = 0; jn < 8; jn++) {
                float* sv = s[it][jn];
                sv[0] = __expf(sv[0] - mrow[it][0]);
                sv[1] = __expf(sv[1] - mrow[it][0]);
                sv[2] = __expf(sv[2] - mrow[it][1]);
                sv[3] = __expf(sv[3] - mrow[it][1]);
                ls0 += sv[0] + sv[1];
                ls1 += sv[2] + sv[3];
            }
            rsum[it][0] += ls0;
            rsum[it][1] += ls1;
            #pragma unroll
            for (int kk = 0; kk < 4; kk++) {
                split2(s[it][2 * kk][0],     s[it][2 * kk][1],
                       pfh[it][kk][0], pfl[it][kk][0]);
                split2(s[it][2 * kk][2],     s[it][2 * kk][3],
                       pfh[it][kk][1], pfl[it][kk][1]);
                split2(s[it][2 * kk + 1][0], s[it][2 * kk + 1][1],
                       pfh[it][kk][2], pfl[it][kk][2]);
                split2(s[it][2 * kk + 1][2], s[it][2 * kk + 1][3],
                       pfh[it][kk][3], pfl[it][kk][3]);
            }
        }

        // ---- out += P @ V (3-term bf16 split; V via ldmatrix.trans) ----
        #pragma unroll
        for (int kk = 0; kk < 4; kk++) {
            #pragma unroll
            for (int np = 0; np < 4; np++) {
                uint32_t vhf[4], vlf[4];
                uint32_t off = (uint32_t)((jc + kk * 16 + qRO) * ASTRIDE
                                          + np * 16 + qCO) * 2;
                ldm_x4_t(vhf, aVh + off);
                ldm_x4_t(vlf, aVl + off);
                #pragma unroll
                for (int it = 0; it < 2; it++) {
                    mma16816(out[it][2 * np],     pfh[it][kk], vhf);
                    mma16816(out[it][2 * np],     pfl[it][kk], vhf);
                    mma16816(out[it][2 * np],     pfh[it][kk], vlf);
                    mma16816(out[it][2 * np + 1], pfh[it][kk], vhf + 2);
                    mma16816(out[it][2 * np + 1], pfl[it][kk], vhf + 2);
                    mma16816(out[it][2 * np + 1], pfh[it][kk], vlf + 2);
                }
            }
        }
    }

    // ---- finalize: normalize by row sums, store ----
    #pragma unroll
    for (int it = 0; it < 2; it++) {
        float s0 = rsum[it][0];
        s0 += __shfl_xor_sync(0xffffffffu, s0, 1);
        s0 += __shfl_xor_sync(0xffffffffu, s0, 2);
        float s1 = rsum[it][1];
        s1 += __shfl_xor_sync(0xffffffffu, s1, 1);
        s1 += __shfl_xor_sync(0xffffffffu, s1, 2);
        float inv0 = 1.f / s0, inv1 = 1.f / s1;
        int r0 = i0 + it * 16 + g, r1 = r0 + 8;
        #pragma unroll
        for (int jn = 0; jn < 8; jn++) {
            int d = jn * 8 + 2 * tig;
            if (r0 < NTOK) {
                float2 v = make_float2(out[it][jn][0] * inv0,
                                       out[it][jn][1] * inv0);
                *(float2*)(gout + (size_t)(b * NTOK + r0) * INNER
                           + h * DHEAD + d) = v;
            }
            if (r1 < NTOK) {
                float2 v = make_float2(out[it][jn][2] * inv1,
                                       out[it][jn][3] * inv1);
                *(float2*)(gout + (size_t)(b * NTOK + r1) * INNER
                           + h * DHEAD + d) = v;
            }
        }
    }
}

// ---------------- launch ----------------
extern "C" void kernel_launch(void* const* d_in, const int* in_sizes, int n_in,
                              void* d_out, int out_size)
{
    const float* x       = (const float*)d_in[0];
    const float* pos_emb = (const float*)d_in[1];
    const float* w_qkv   = (const float*)d_in[2];
    const float* scale   = (const float*)d_in[3];
    const float* w_out   = (const float*)d_in[4];
    const float* b_out   = (const float*)d_in[5];
    float* out = (float*)d_out;

    float *qkv, *q, *k, *v, *att, *wqkvT, *woutT;
    cudaGetSymbolAddress((void**)&qkv,   g_qkv);
    cudaGetSymbolAddress((void**)&q,     g_q);
    cudaGetSymbolAddress((void**)&k,     g_k);
    cudaGetSymbolAddress((void**)&v,     g_v);
    cudaGetSymbolAddress((void**)&att,   g_att);
    cudaGetSymbolAddress((void**)&wqkvT, g_wqkvT);
    cudaGetSymbolAddress((void**)&woutT, g_woutT);

    cudaFuncSetAttribute(attention_mma,
                         cudaFuncAttributeMaxDynamicSharedMemorySize,
                         ATT_MMA_SMEM);

    // 0) transpose weights to [N, K]
    transpose_kernel<<<dim3(QKVCOLS / 32, DIM / 32), dim3(32, 8)>>>(
        w_qkv, wqkvT, DIM, QKVCOLS);
    transpose_kernel<<<dim3(DIM / 32, INNER / 32), dim3(32, 8)>>>(
        w_out, woutT, INNER, DIM);

    // 1) qkv = x @ w_qkv
    gemm_bf16x3<<<dim3(QKVCOLS / 128, (MROWS + 127) / 128), 256>>>(
        x, wqkvT, nullptr, qkv, MROWS, QKVCOLS, DIM);

    // 2) rotary + scale + scatter
    {
        int total = MROWS * 384;
        rotary_scatter_kernel<<<(total + 255) / 256, 256>>>(qkv, pos_emb, scale,
                                                            q, k, v);
    }

    // 3) attention (tensor-core)
    attention_mma<<<BATCH * HEADS, 224, ATT_MMA_SMEM>>>(q, k, v, att);

    // 4) out = att @ w_out + b_out
    gemm_bf16x3<<<dim3(DIM / 128, (MROWS + 127) / 128), 256>>>(
        att, woutT, b_out, out, MROWS, DIM, INNER);
}

// round 9
// speedup vs baseline: 2.0004x; 1.3194x over previous
#include <cuda_runtime.h>
#include <cuda_bf16.h>
#include <cstdint>
#include <math.h>

// ---------------- problem constants ----------------
constexpr int BATCH   = 64;
constexpr int NTOK    = 197;
constexpr int DIM     = 768;
constexpr int HEADS   = 12;
constexpr int DHEAD   = 64;
constexpr int INNER   = HEADS * DHEAD;      // 768
constexpr int MROWS   = BATCH * NTOK;       // 12608 = 64 * 197
constexpr int QKVCOLS = 3 * INNER;          // 2304
constexpr float MASK_FILL = -987654321.0f;

// ---------------- scratch (device globals) ----------------
__device__ float g_qkv[(size_t)MROWS * QKVCOLS];
__device__ float g_q[(size_t)BATCH * HEADS * NTOK * DHEAD];
__device__ float g_k[(size_t)BATCH * HEADS * NTOK * DHEAD];
__device__ float g_v[(size_t)BATCH * HEADS * NTOK * DHEAD];
__device__ float g_att[(size_t)MROWS * INNER];
// pre-split bf16 operands (16B-aligned: vector ld/st safety)
__device__ __align__(16) __nv_bfloat16 g_Ah[(size_t)MROWS * DIM];
__device__ __align__(16) __nv_bfloat16 g_Al[(size_t)MROWS * DIM];
__device__ __align__(16) __nv_bfloat16 g_Wqh[(size_t)QKVCOLS * DIM];
__device__ __align__(16) __nv_bfloat16 g_Wql[(size_t)QKVCOLS * DIM];
__device__ __align__(16) __nv_bfloat16 g_Woh[(size_t)DIM * INNER];
__device__ __align__(16) __nv_bfloat16 g_Wol[(size_t)DIM * INNER];

// ---------------- helpers ----------------
__device__ __forceinline__ void split2(float x, float y,
                                       uint32_t& hi, uint32_t& lo) {
    __nv_bfloat16 hx = __float2bfloat16_rn(x);
    __nv_bfloat16 hy = __float2bfloat16_rn(y);
    __nv_bfloat162 hp;
    hp.x = hx; hp.y = hy;
    hi = *reinterpret_cast<uint32_t*>(&hp);
    __nv_bfloat162 lp;
    lp.x = __float2bfloat16_rn(x - __bfloat162float(hx));
    lp.y = __float2bfloat16_rn(y - __bfloat162float(hy));
    lo = *reinterpret_cast<uint32_t*>(&lp);
}

__device__ __forceinline__ void mma16816(float* c, const uint32_t* a,
                                         const uint32_t* b) {
    asm volatile(
        "mma.sync.aligned.m16n8k16.row.col.f32.bf16.bf16.f32 "
        "{%0,%1,%2,%3}, {%4,%5,%6,%7}, {%8,%9}, {%0,%1,%2,%3};"
        : "+f"(c[0]), "+f"(c[1]), "+f"(c[2]), "+f"(c[3])
        : "r"(a[0]), "r"(a[1]), "r"(a[2]), "r"(a[3]),
          "r"(b[0]), "r"(b[1]));
}

__device__ __forceinline__ void ldm_x4(uint32_t* r, uint32_t addr) {
    asm volatile("ldmatrix.sync.aligned.m8n8.x4.shared.b16 {%0,%1,%2,%3}, [%4];"
        : "=r"(r[0]), "=r"(r[1]), "=r"(r[2]), "=r"(r[3]) : "r"(addr));
}

__device__ __forceinline__ void ldm_x4_t(uint32_t* r, uint32_t addr) {
    asm volatile("ldmatrix.sync.aligned.m8n8.x4.trans.shared.b16 {%0,%1,%2,%3}, [%4];"
        : "=r"(r[0]), "=r"(r[1]), "=r"(r[2]), "=r"(r[3]) : "r"(addr));
}

__device__ __forceinline__ uint32_t smem_u32(const void* p) {
    uint32_t a;
    asm("{ .reg .u64 t; cvta.to.shared.u64 t, %1; cvt.u32.u64 %0, t; }"
        : "=r"(a) : "l"(p));
    return a;
}

__device__ __forceinline__ void cpa16(uint32_t dst, const void* src) {
    asm volatile("cp.async.cg.shared.global [%0], [%1], 16;"
        :: "r"(dst), "l"(src));
}

// ---------------- pre-split kernels ----------------
// fp32 -> bf16 hi/lo, 4 elements per thread
__global__ __launch_bounds__(256) void split_kernel(
    const float* __restrict__ src, __nv_bfloat16* __restrict__ hi,
    __nv_bfloat16* __restrict__ lo, int n4)
{
    int i = blockIdx.x * blockDim.x + threadIdx.x;
    if (i >= n4) return;
    float4 v = ((const float4*)src)[i];
    uint32_t h0, l0, h1, l1;
    split2(v.x, v.y, h0, l0);
    split2(v.z, v.w, h1, l1);
    ((uint2*)hi)[i] = make_uint2(h0, h1);
    ((uint2*)lo)[i] = make_uint2(l0, l1);
}

// transpose + split: src fp32 [R][C] -> dst bf16 hi/lo [C][R]
__global__ void transpose_split_kernel(
    const float* __restrict__ src, __nv_bfloat16* __restrict__ dhi,
    __nv_bfloat16* __restrict__ dlo, int R, int C)
{
    __shared__ float t[32][33];
    int c0 = blockIdx.x * 32, r0 = blockIdx.y * 32;
    int x = threadIdx.x, y = threadIdx.y;   // (32, 8)
    #pragma unroll
    for (int i = 0; i < 32; i += 8)
        t[y + i][x] = src[(size_t)(r0 + y + i) * C + c0 + x];
    __syncthreads();
    #pragma unroll
    for (int i = 0; i < 32; i += 8) {
        float v = t[x][y + i];
        __nv_bfloat16 h = __float2bfloat16_rn(v);
        size_t o = (size_t)(c0 + y + i) * R + r0 + x;
        dhi[o] = h;
        dlo[o] = __float2bfloat16_rn(v - __bfloat162float(h));
    }
}

// ---------------- pre-split bf16 GEMM ----------------
// C[M,N] = (Ah+Al)[M,K] @ (Bh+Bl)[N,K]^T (+bias), 3-term split product.
// CTA tile 64x128, k-chunk 64, 2-stage cp.async. Requires M%64==0, N%128==0,
// K%64==0. 256 threads: 2 m-warps x 4 n-warps, warp tile 32x32.
// smem stage: Ah 8K | Al 8K | Bh 16K | Bl 16K = 48KB. Rows are 128B, SW128.
constexpr int GSTAGE    = 49152;
constexpr int GEMM_SMEM = 2 * GSTAGE;    // 96 KB -> 2 CTAs/SM

__global__ __launch_bounds__(256) void gemm_bf16p(
    const __nv_bfloat16* __restrict__ Ah, const __nv_bfloat16* __restrict__ Al,
    const __nv_bfloat16* __restrict__ Bh, const __nv_bfloat16* __restrict__ Bl,
    const float* __restrict__ bias, float* __restrict__ C,
    int M, int N, int K)
{
    extern __shared__ uint8_t dynsm[];
    const uint32_t sb = smem_u32(dynsm);
    const int tid  = threadIdx.x;
    const int lane = tid & 31;
    const int wid  = tid >> 5;
    const int g    = lane >> 2;
    const int tig  = lane & 3;
    const int wm   = wid & 1;
    const int wn   = wid >> 1;
    const int mBase = blockIdx.y * 64;
    const int nBase = blockIdx.x * 128;
    const int KC = K >> 6;

    // ldmatrix per-lane row/col16 offsets
    const int aRow = lane & 15;
    const int aC   = lane >> 4;
    const int bRow = (lane & 7) + ((lane & 16) >> 1);
    const int bC   = (lane >> 3) & 1;

    float acc[2][4][4];
    #pragma unroll
    for (int i = 0; i < 2; i++)
        #pragma unroll
        for (int j = 0; j < 4; j++)
            #pragma unroll
            for (int r = 0; r < 4; r++) acc[i][j][r] = 0.f;

    auto stage_load = [&](int kc, int s) {
        const uint32_t st = sb + s * GSTAGE;
        #pragma unroll
        for (int p = 0; p < 2; p++) {       // A: 64 rows x 8 chunks
            int idx = tid + p * 256;
            int r = idx >> 3, c = idx & 7;
            uint32_t phys = (uint32_t)(r * 128 + ((c ^ (r & 7)) << 4));
            size_t go = (size_t)(mBase + r) * K + kc * 64 + c * 8;
            cpa16(st + phys,        Ah + go);
            cpa16(st + 8192 + phys, Al + go);
        }
        #pragma unroll
        for (int p = 0; p < 4; p++) {       // B: 128 rows x 8 chunks
            int idx = tid + p * 256;
            int r = idx >> 3, c = idx & 7;
            uint32_t phys = (uint32_t)(r * 128 + ((c ^ (r & 7)) << 4));
            size_t go = (size_t)(nBase + r) * K + kc * 64 + c * 8;
            cpa16(st + 16384 + phys, Bh + go);
            cpa16(st + 32768 + phys, Bl + go);
        }
    };

    stage_load(0, 0);
    asm volatile("cp.async.commit_group;" ::: "memory");
    if (KC > 1) {
        stage_load(1, 1);
        asm volatile("cp.async.commit_group;" ::: "memory");
    }

    for (int kc = 0; kc < KC; kc++) {
        const int s = kc & 1;
        if (kc == KC - 1)
            asm volatile("cp.async.wait_group 0;" ::: "memory");
        else
            asm volatile("cp.async.wait_group 1;" ::: "memory");
        __syncthreads();

        const uint32_t stA  = sb + s * GSTAGE;
        const uint32_t stAl = stA + 8192;
        const uint32_t stB  = stA + 16384;
        const uint32_t stBl = stA + 32768;

        #pragma unroll
        for (int kk = 0; kk < 4; kk++) {
            uint32_t fah[2][4], fal[2][4], fbh[2][4], fbl[2][4];
            #pragma unroll
            for (int i = 0; i < 2; i++) {
                int row = wm * 32 + i * 16 + aRow;
                int c16 = kk * 2 + aC;
                uint32_t phys = (uint32_t)(row * 128 + ((c16 ^ (row & 7)) << 4));
                ldm_x4(fah[i], stA  + phys);
                ldm_x4(fal[i], stAl + phys);
            }
            #pragma unroll
            for (int j = 0; j < 2; j++) {
                int row = wn * 32 + j * 16 + bRow;
                int c16 = kk * 2 + bC;
                uint32_t phys = (uint32_t)(row * 128 + ((c16 ^ (row & 7)) << 4));
                ldm_x4(fbh[j], stB  + phys);
                ldm_x4(fbl[j], stBl + phys);
            }
            #pragma unroll
            for (int i = 0; i < 2; i++)
                #pragma unroll
                for (int j = 0; j < 2; j++)
                    #pragma unroll
                    for (int jj = 0; jj < 2; jj++) {
                        float* a = acc[i][j * 2 + jj];
                        mma16816(a, fah[i], fbh[j] + jj * 2);
                        mma16816(a, fal[i], fbh[j] + jj * 2);
                        mma16816(a, fah[i], fbl[j] + jj * 2);
                    }
        }
        __syncthreads();

        if (kc + 2 < KC) {
            stage_load(kc + 2, s);
            asm volatile("cp.async.commit_group;" ::: "memory");
        }
    }

    // epilogue (M%64==0, no guards)
    #pragma unroll
    for (int i = 0; i < 2; i++) {
        int r0 = mBase + wm * 32 + i * 16 + g;
        #pragma unroll
        for (int j = 0; j < 4; j++) {
            int c = nBase + wn * 32 + j * 8 + 2 * tig;
            float b0 = bias ? bias[c]     : 0.f;
            float b1 = bias ? bias[c + 1] : 0.f;
            *(float2*)(C + (size_t)r0 * N + c) =
                make_float2(acc[i][j][0] + b0, acc[i][j][1] + b1);
            *(float2*)(C + (size_t)(r0 + 8) * N + c) =
                make_float2(acc[i][j][2] + b0, acc[i][j][3] + b1);
        }
    }
}

// ---------------- rotary + scale + scatter ----------------
__global__ __launch_bounds__(256) void rotary_scatter_kernel(
    const float* __restrict__ qkv, const float* __restrict__ pos_emb,
    const float* __restrict__ scale,
    float* __restrict__ q, float* __restrict__ k, float* __restrict__ v)
{
    int idx = blockIdx.x * blockDim.x + threadIdx.x;
    if (idx >= MROWS * 384) return;
    int m = idx / 384;
    int p = idx - m * 384;
    int h = p >> 5;
    int t = p & 31;
    int i = m % NTOK;
    int b = m / NTOK;

    float sn = pos_emb[i * DHEAD + t];
    float cs = pos_emb[i * DHEAD + 32 + t];

    const float* row = qkv + (size_t)m * QKVCOLS;
    int col = h * DHEAD + 2 * t;
    float q0 = row[col],             q1 = row[col + 1];
    float k0 = row[INNER + col],     k1 = row[INNER + col + 1];
    float v0 = row[2 * INNER + col], v1 = row[2 * INNER + col + 1];
    float sc = scale[h];

    size_t dst = (((size_t)(b * HEADS + h)) * NTOK + i) * DHEAD + 2 * t;
    q[dst]     = (q0 * cs - q1 * sn) * sc;
    q[dst + 1] = (q1 * cs + q0 * sn) * sc;
    k[dst]     = k0 * cs - k1 * sn;
    k[dst + 1] = k1 * cs + k0 * sn;
    v[dst]     = v0;
    v[dst + 1] = v1;
}

// ---------------- MMA attention: one block per (b, h) ----------------
constexpr int ASTRIDE   = 72;
constexpr int Q_TILE_H  = 224 * ASTRIDE;
constexpr int KV_TILE_H = 256 * ASTRIDE;
constexpr int ATT_MMA_SMEM = (2 * Q_TILE_H + 4 * KV_TILE_H) * 2;  // 211968 B

__device__ __forceinline__ float maskv(float v, int r, int c) {
    if (c == r)     return MASK_FILL;
    if (c >= NTOK)  return -1e30f;
    return v;
}

__global__ __launch_bounds__(224, 1) void attention_mma(
    const float* __restrict__ gq, const float* __restrict__ gk,
    const float* __restrict__ gv, float* __restrict__ gout)
{
    extern __shared__ uint8_t dynsm[];
    __nv_bfloat16* sbb = (__nv_bfloat16*)dynsm;
    __nv_bfloat16* sQh = sbb;
    __nv_bfloat16* sQl = sbb + Q_TILE_H;
    __nv_bfloat16* sKh = sbb + 2 * Q_TILE_H;
    __nv_bfloat16* sKl = sKh + KV_TILE_H;
    __nv_bfloat16* sVh = sKh + 2 * KV_TILE_H;
    __nv_bfloat16* sVl = sKh + 3 * KV_TILE_H;

    const int bh   = blockIdx.x;
    const int b    = bh / HEADS;
    const int h    = bh - b * HEADS;
    const int tid  = threadIdx.x;
    const int w    = tid >> 5;
    const int lane = tid & 31;
    const int g    = lane >> 2;
    const int tig  = lane & 3;
    const size_t base = (size_t)bh * NTOK * DHEAD;

    for (int idx = tid; idx < 256 * DHEAD; idx += 224) {
        int row = idx >> 6;
        float kv = 0.f, vv = 0.f;
        if (row < NTOK) { kv = gk[base + idx]; vv = gv[base + idx]; }
        int o = row * ASTRIDE + (idx & 63);
        __nv_bfloat16 t;
        t = __float2bfloat16_rn(kv);
        sKh[o] = t;
        sKl[o] = __float2bfloat16_rn(kv - __bfloat162float(t));
        t = __float2bfloat16_rn(vv);
        sVh[o] = t;
        sVl[o] = __float2bfloat16_rn(vv - __bfloat162float(t));
        if (row < 224) {
            float qv = (row < NTOK) ? gq[base + idx] : 0.f;
            t = __float2bfloat16_rn(qv);
            sQh[o] = t;
            sQl[o] = __float2bfloat16_rn(qv - __bfloat162float(t));
        }
    }
    __syncthreads();

    const uint32_t aQh = smem_u32(sQh), aQl = smem_u32(sQl);
    const uint32_t aKh = smem_u32(sKh), aKl = smem_u32(sKl);
    const uint32_t aVh = smem_u32(sVh), aVl = smem_u32(sVl);

    const int qRO = (lane & 7) + ((lane & 8)  ? 8 : 0);
    const int qCO = (lane & 16) ? 8 : 0;
    const int kRO = (lane & 7) + ((lane & 16) ? 8 : 0);
    const int kCO = (lane & 8)  ? 8 : 0;
    const int i0  = w * 32;

    float out[2][8][4];
    #pragma unroll
    for (int it = 0; it < 2; it++)
        #pragma unroll
        for (int jn = 0; jn < 8; jn++)
            #pragma unroll
            for (int r = 0; r < 4; r++) out[it][jn][r] = 0.f;

    float mrow[2][2] = {{-INFINITY, -INFINITY}, {-INFINITY, -INFINITY}};
    float rsum[2][2] = {{0.f, 0.f}, {0.f, 0.f}};

    for (int c = 0; c < 4; c++) {
        const int jc = c * 64;
        float s[2][8][4];
        #pragma unroll
        for (int it = 0; it < 2; it++)
            #pragma unroll
            for (int jn = 0; jn < 8; jn++)
                #pragma unroll
                for (int r = 0; r < 4; r++) s[it][jn][r] = 0.f;

        #pragma unroll
        for (int kk = 0; kk < 4; kk++) {
            uint32_t qh[2][4], ql[2][4];
            #pragma unroll
            for (int it = 0; it < 2; it++) {
                uint32_t off = (uint32_t)((i0 + it * 16 + qRO) * ASTRIDE
                                          + kk * 16 + qCO) * 2;
                ldm_x4(qh[it], aQh + off);
                ldm_x4(ql[it], aQl + off);
            }
            #pragma unroll
            for (int np = 0; np < 4; np++) {
                uint32_t khf[4], klf[4];
                uint32_t off = (uint32_t)((jc + np * 16 + kRO) * ASTRIDE
                                          + kk * 16 + kCO) * 2;
                ldm_x4(khf, aKh + off);
                ldm_x4(klf, aKl + off);
                #pragma unroll
                for (int it = 0; it < 2; it++) {
                    mma16816(s[it][2 * np],     qh[it], khf);
                    mma16816(s[it][2 * np],     ql[it], khf);
                    mma16816(s[it][2 * np],     qh[it], klf);
                    mma16816(s[it][2 * np + 1], qh[it], khf + 2);
                    mma16816(s[it][2 * np + 1], ql[it], khf + 2);
                    mma16816(s[it][2 * np + 1], qh[it], klf + 2);
                }
            }
        }

        float cm[2][2] = {{-INFINITY, -INFINITY}, {-INFINITY, -INFINITY}};
        #pragma unroll
        for (int it = 0; it < 2; it++) {
            int r0 = i0 + it * 16 + g;
            int r1 = r0 + 8;
            #pragma unroll
            for (int jn = 0; jn < 8; jn++) {
                int cb = jc + jn * 8 + 2 * tig;
                float* sv = s[it][jn];
                sv[0] = maskv(sv[0], r0, cb);
                sv[1] = maskv(sv[1], r0, cb + 1);
                sv[2] = maskv(sv[2], r1, cb);
                sv[3] = maskv(sv[3], r1, cb + 1);
                cm[it][0] = fmaxf(cm[it][0], fmaxf(sv[0], sv[1]));
                cm[it][1] = fmaxf(cm[it][1], fmaxf(sv[2], sv[3]));
            }
        }
        #pragma unroll
        for (int it = 0; it < 2; it++)
            #pragma unroll
            for (int hf = 0; hf < 2; hf++) {
                float v = cm[it][hf];
                v = fmaxf(v, __shfl_xor_sync(0xffffffffu, v, 1));
                v = fmaxf(v, __shfl_xor_sync(0xffffffffu, v, 2));
                float mnew = fmaxf(mrow[it][hf], v);
                float sc = __expf(mrow[it][hf] - mnew);
                mrow[it][hf] = mnew;
                rsum[it][hf] *= sc;
                #pragma unroll
                for (int jn = 0; jn < 8; jn++) {
                    out[it][jn][hf * 2]     *= sc;
                    out[it][jn][hf * 2 + 1] *= sc;
                }
            }

        uint32_t pfh[2][4][4], pfl[2][4][4];
        #pragma unroll
        for (int it = 0; it < 2; it++) {
            float ls0 = 0.f, ls1 = 0.f;
            #pragma unroll
            for (int jn = 0; jn < 8; jn++) {
                float* sv = s[it][jn];
                sv[0] = __expf(sv[0] - mrow[it][0]);
                sv[1] = __expf(sv[1] - mrow[it][0]);
                sv[2] = __expf(sv[2] - mrow[it][1]);
                sv[3] = __expf(sv[3] - mrow[it][1]);
                ls0 += sv[0] + sv[1];
                ls1 += sv[2] + sv[3];
            }
            rsum[it][0] += ls0;
            rsum[it][1] += ls1;
            #pragma unroll
            for (int kk = 0; kk < 4; kk++) {
                split2(s[it][2 * kk][0],     s[it][2 * kk][1],
                       pfh[it][kk][0], pfl[it][kk][0]);
                split2(s[it][2 * kk][2],     s[it][2 * kk][3],
                       pfh[it][kk][1], pfl[it][kk][1]);
                split2(s[it][2 * kk + 1][0], s[it][2 * kk + 1][1],
                       pfh[it][kk][2], pfl[it][kk][2]);
                split2(s[it][2 * kk + 1][2], s[it][2 * kk + 1][3],
                       pfh[it][kk][3], pfl[it][kk][3]);
            }
        }

        #pragma unroll
        for (int kk = 0; kk < 4; kk++) {
            #pragma unroll
            for (int np = 0; np < 4; np++) {
                uint32_t vhf[4], vlf[4];
                uint32_t off = (uint32_t)((jc + kk * 16 + qRO) * ASTRIDE
                                          + np * 16 + qCO) * 2;
                ldm_x4_t(vhf, aVh + off);
                ldm_x4_t(vlf, aVl + off);
                #pragma unroll
                for (int it = 0; it < 2; it++) {
                    mma16816(out[it][2 * np],     pfh[it][kk], vhf);
                    mma16816(out[it][2 * np],     pfl[it][kk], vhf);
                    mma16816(out[it][2 * np],     pfh[it][kk], vlf);
                    mma16816(out[it][2 * np + 1], pfh[it][kk], vhf + 2);
                    mma16816(out[it][2 * np + 1], pfl[it][kk], vhf + 2);
                    mma16816(out[it][2 * np + 1], pfh[it][kk], vlf + 2);
                }
            }
        }
    }

    #pragma unroll
    for (int it = 0; it < 2; it++) {
        float s0 = rsum[it][0];
        s0 += __shfl_xor_sync(0xffffffffu, s0, 1);
        s0 += __shfl_xor_sync(0xffffffffu, s0, 2);
        float s1 = rsum[it][1];
        s1 += __shfl_xor_sync(0xffffffffu, s1, 1);
        s1 += __shfl_xor_sync(0xffffffffu, s1, 2);
        float inv0 = 1.f / s0, inv1 = 1.f / s1;
        int r0 = i0 + it * 16 + g, r1 = r0 + 8;
        #pragma unroll
        for (int jn = 0; jn < 8; jn++) {
            int d = jn * 8 + 2 * tig;
            if (r0 < NTOK) {
                float2 v = make_float2(out[it][jn][0] * inv0,
                                       out[it][jn][1] * inv0);
                *(float2*)(gout + (size_t)(b * NTOK + r0) * INNER
                           + h * DHEAD + d) = v;
            }
            if (r1 < NTOK) {
                float2 v = make_float2(out[it][jn][2] * inv1,
                                       out[it][jn][3] * inv1);
                *(float2*)(gout + (size_t)(b * NTOK + r1) * INNER
                           + h * DHEAD + d) = v;
            }
        }
    }
}

// ---------------- launch ----------------
extern "C" void kernel_launch(void* const* d_in, const int* in_sizes, int n_in,
                              void* d_out, int out_size)
{
    const float* x       = (const float*)d_in[0];
    const float* pos_emb = (const float*)d_in[1];
    const float* w_qkv   = (const float*)d_in[2];
    const float* scale   = (const float*)d_in[3];
    const float* w_out   = (const float*)d_in[4];
    const float* b_out   = (const float*)d_in[5];
    float* out = (float*)d_out;

    float *qkv, *q, *k, *v, *att;
    __nv_bfloat16 *ah, *al, *wqh, *wql, *woh, *wol;
    cudaGetSymbolAddress((void**)&qkv, g_qkv);
    cudaGetSymbolAddress((void**)&q,   g_q);
    cudaGetSymbolAddress((void**)&k,   g_k);
    cudaGetSymbolAddress((void**)&v,   g_v);
    cudaGetSymbolAddress((void**)&att, g_att);
    cudaGetSymbolAddress((void**)&ah,  g_Ah);
    cudaGetSymbolAddress((void**)&al,  g_Al);
    cudaGetSymbolAddress((void**)&wqh, g_Wqh);
    cudaGetSymbolAddress((void**)&wql, g_Wql);
    cudaGetSymbolAddress((void**)&woh, g_Woh);
    cudaGetSymbolAddress((void**)&wol, g_Wol);

    cudaFuncSetAttribute(attention_mma,
                         cudaFuncAttributeMaxDynamicSharedMemorySize,
                         ATT_MMA_SMEM);
    cudaFuncSetAttribute(gemm_bf16p,
                         cudaFuncAttributeMaxDynamicSharedMemorySize,
                         GEMM_SMEM);

    // 0) weights: transpose + split to bf16 hi/lo [N,K]
    transpose_split_kernel<<<dim3(QKVCOLS / 32, DIM / 32), dim3(32, 8)>>>(
        w_qkv, wqh, wql, DIM, QKVCOLS);
    transpose_split_kernel<<<dim3(DIM / 32, INNER / 32), dim3(32, 8)>>>(
        w_out, woh, wol, INNER, DIM);

    // 1) x -> bf16 hi/lo, then qkv = x @ w_qkv
    {
        int n4 = MROWS * DIM / 4;
        split_kernel<<<(n4 + 255) / 256, 256>>>(x, ah, al, n4);
    }
    gemm_bf16p<<<dim3(QKVCOLS / 128, MROWS / 64), 256, GEMM_SMEM>>>(
        ah, al, wqh, wql, nullptr, qkv, MROWS, QKVCOLS, DIM);

    // 2) rotary + scale + scatter
    {
        int total = MROWS * 384;
        rotary_scatter_kernel<<<(total + 255) / 256, 256>>>(qkv, pos_emb, scale,
                                                            q, k, v);
    }

    // 3) attention (tensor-core)
    attention_mma<<<BATCH * HEADS, 224, ATT_MMA_SMEM>>>(q, k, v, att);

    // 4) att -> bf16 hi/lo, then out = att @ w_out + b_out
    {
        int n4 = MROWS * INNER / 4;
        split_kernel<<<(n4 + 255) / 256, 256>>>(att, ah, al, n4);
    }
    gemm_bf16p<<<dim3(DIM / 128, MROWS / 64), 256, GEMM_SMEM>>>(
        ah, al, woh, wol, b_out, out, MROWS, DIM, INNER);
}

// round 10
// speedup vs baseline: 3.0952x; 1.5473x over previous
#include <cuda_runtime.h>
#include <cuda_bf16.h>
#include <cstdint>
#include <math.h>

// ---------------- problem constants ----------------
constexpr int BATCH   = 64;
constexpr int NTOK    = 197;
constexpr int DIM     = 768;
constexpr int HEADS   = 12;
constexpr int DHEAD   = 64;
constexpr int INNER   = HEADS * DHEAD;      // 768
constexpr int MROWS   = BATCH * NTOK;       // 12608 = 64 * 197
constexpr int QKVCOLS = 3 * INNER;          // 2304
constexpr int BHN     = BATCH * HEADS * NTOK * DHEAD;
constexpr float MASK_FILL = -987654321.0f;

// ---------------- scratch (device globals) ----------------
__device__ float g_qkv[(size_t)MROWS * QKVCOLS];
__device__ float g_att[(size_t)MROWS * INNER];
// pre-split bf16 operands (16B-aligned)
__device__ __align__(16) __nv_bfloat16 g_Ah[(size_t)MROWS * DIM];
__device__ __align__(16) __nv_bfloat16 g_Al[(size_t)MROWS * DIM];
__device__ __align__(16) __nv_bfloat16 g_Wqh[(size_t)QKVCOLS * DIM];
__device__ __align__(16) __nv_bfloat16 g_Wql[(size_t)QKVCOLS * DIM];
__device__ __align__(16) __nv_bfloat16 g_Woh[(size_t)DIM * INNER];
__device__ __align__(16) __nv_bfloat16 g_Wol[(size_t)DIM * INNER];
// pre-split rotary outputs [bh][n][dh]
__device__ __align__(16) __nv_bfloat16 g_qh[BHN];
__device__ __align__(16) __nv_bfloat16 g_ql[BHN];
__device__ __align__(16) __nv_bfloat16 g_kh[BHN];
__device__ __align__(16) __nv_bfloat16 g_kl[BHN];
__device__ __align__(16) __nv_bfloat16 g_vh[BHN];
__device__ __align__(16) __nv_bfloat16 g_vl[BHN];

// ---------------- helpers ----------------
__device__ __forceinline__ void split2(float x, float y,
                                       uint32_t& hi, uint32_t& lo) {
    __nv_bfloat16 hx = __float2bfloat16_rn(x);
    __nv_bfloat16 hy = __float2bfloat16_rn(y);
    __nv_bfloat162 hp;
    hp.x = hx; hp.y = hy;
    hi = *reinterpret_cast<uint32_t*>(&hp);
    __nv_bfloat162 lp;
    lp.x = __float2bfloat16_rn(x - __bfloat162float(hx));
    lp.y = __float2bfloat16_rn(y - __bfloat162float(hy));
    lo = *reinterpret_cast<uint32_t*>(&lp);
}

__device__ __forceinline__ void mma16816(float* c, const uint32_t* a,
                                         const uint32_t* b) {
    asm volatile(
        "mma.sync.aligned.m16n8k16.row.col.f32.bf16.bf16.f32 "
        "{%0,%1,%2,%3}, {%4,%5,%6,%7}, {%8,%9}, {%0,%1,%2,%3};"
        : "+f"(c[0]), "+f"(c[1]), "+f"(c[2]), "+f"(c[3])
        : "r"(a[0]), "r"(a[1]), "r"(a[2]), "r"(a[3]),
          "r"(b[0]), "r"(b[1]));
}

__device__ __forceinline__ void ldm_x4(uint32_t* r, uint32_t addr) {
    asm volatile("ldmatrix.sync.aligned.m8n8.x4.shared.b16 {%0,%1,%2,%3}, [%4];"
        : "=r"(r[0]), "=r"(r[1]), "=r"(r[2]), "=r"(r[3]) : "r"(addr));
}

__device__ __forceinline__ void ldm_x4_t(uint32_t* r, uint32_t addr) {
    asm volatile("ldmatrix.sync.aligned.m8n8.x4.trans.shared.b16 {%0,%1,%2,%3}, [%4];"
        : "=r"(r[0]), "=r"(r[1]), "=r"(r[2]), "=r"(r[3]) : "r"(addr));
}

__device__ __forceinline__ uint32_t smem_u32(const void* p) {
    uint32_t a;
    asm("{ .reg .u64 t; cvta.to.shared.u64 t, %1; cvt.u32.u64 %0, t; }"
        : "=r"(a) : "l"(p));
    return a;
}

__device__ __forceinline__ void cpa16(uint32_t dst, const void* src) {
    asm volatile("cp.async.cg.shared.global [%0], [%1], 16;"
        :: "r"(dst), "l"(src));
}

__device__ __forceinline__ void cpa16z(uint32_t dst, const void* src, int vb) {
    asm volatile("cp.async.cg.shared.global [%0], [%1], 16, %2;"
        :: "r"(dst), "l"(src), "r"(vb));
}

// ---------------- pre-split kernels ----------------
__global__ __launch_bounds__(256) void split_kernel(
    const float* __restrict__ src, __nv_bfloat16* __restrict__ hi,
    __nv_bfloat16* __restrict__ lo, int n4)
{
    int i = blockIdx.x * blockDim.x + threadIdx.x;
    if (i >= n4) return;
    float4 v = ((const float4*)src)[i];
    uint32_t h0, l0, h1, l1;
    split2(v.x, v.y, h0, l0);
    split2(v.z, v.w, h1, l1);
    ((uint2*)hi)[i] = make_uint2(h0, h1);
    ((uint2*)lo)[i] = make_uint2(l0, l1);
}

__global__ void transpose_split_kernel(
    const float* __restrict__ src, __nv_bfloat16* __restrict__ dhi,
    __nv_bfloat16* __restrict__ dlo, int R, int C)
{
    __shared__ float t[32][33];
    int c0 = blockIdx.x * 32, r0 = blockIdx.y * 32;
    int x = threadIdx.x, y = threadIdx.y;   // (32, 8)
    #pragma unroll
    for (int i = 0; i < 32; i += 8)
        t[y + i][x] = src[(size_t)(r0 + y + i) * C + c0 + x];
    __syncthreads();
    #pragma unroll
    for (int i = 0; i < 32; i += 8) {
        float v = t[x][y + i];
        __nv_bfloat16 h = __float2bfloat16_rn(v);
        size_t o = (size_t)(c0 + y + i) * R + r0 + x;
        dhi[o] = h;
        dlo[o] = __float2bfloat16_rn(v - __bfloat162float(h));
    }
}

// ---------------- pre-split bf16 GEMM (unchanged from R9) ----------------
constexpr int GSTAGE    = 49152;
constexpr int GEMM_SMEM = 2 * GSTAGE;    // 96 KB -> 2 CTAs/SM

__global__ __launch_bounds__(256) void gemm_bf16p(
    const __nv_bfloat16* __restrict__ Ah, const __nv_bfloat16* __restrict__ Al,
    const __nv_bfloat16* __restrict__ Bh, const __nv_bfloat16* __restrict__ Bl,
    const float* __restrict__ bias, float* __restrict__ C,
    int M, int N, int K)
{
    extern __shared__ uint8_t dynsm[];
    const uint32_t sb = smem_u32(dynsm);
    const int tid  = threadIdx.x;
    const int lane = tid & 31;
    const int wid  = tid >> 5;
    const int g    = lane >> 2;
    const int tig  = lane & 3;
    const int wm   = wid & 1;
    const int wn   = wid >> 1;
    const int mBase = blockIdx.y * 64;
    const int nBase = blockIdx.x * 128;
    const int KC = K >> 6;

    const int aRow = lane & 15;
    const int aC   = lane >> 4;
    const int bRow = (lane & 7) + ((lane & 16) >> 1);
    const int bC   = (lane >> 3) & 1;

    float acc[2][4][4];
    #pragma unroll
    for (int i = 0; i < 2; i++)
        #pragma unroll
        for (int j = 0; j < 4; j++)
            #pragma unroll
            for (int r = 0; r < 4; r++) acc[i][j][r] = 0.f;

    auto stage_load = [&](int kc, int s) {
        const uint32_t st = sb + s * GSTAGE;
        #pragma unroll
        for (int p = 0; p < 2; p++) {
            int idx = tid + p * 256;
            int r = idx >> 3, c = idx & 7;
            uint32_t phys = (uint32_t)(r * 128 + ((c ^ (r & 7)) << 4));
            size_t go = (size_t)(mBase + r) * K + kc * 64 + c * 8;
            cpa16(st + phys,        Ah + go);
            cpa16(st + 8192 + phys, Al + go);
        }
        #pragma unroll
        for (int p = 0; p < 4; p++) {
            int idx = tid + p * 256;
            int r = idx >> 3, c = idx & 7;
            uint32_t phys = (uint32_t)(r * 128 + ((c ^ (r & 7)) << 4));
            size_t go = (size_t)(nBase + r) * K + kc * 64 + c * 8;
            cpa16(st + 16384 + phys, Bh + go);
            cpa16(st + 32768 + phys, Bl + go);
        }
    };

    stage_load(0, 0);
    asm volatile("cp.async.commit_group;" ::: "memory");
    if (KC > 1) {
        stage_load(1, 1);
        asm volatile("cp.async.commit_group;" ::: "memory");
    }

    for (int kc = 0; kc < KC; kc++) {
        const int s = kc & 1;
        if (kc == KC - 1)
            asm volatile("cp.async.wait_group 0;" ::: "memory");
        else
            asm volatile("cp.async.wait_group 1;" ::: "memory");
        __syncthreads();

        const uint32_t stA  = sb + s * GSTAGE;
        const uint32_t stAl = stA + 8192;
        const uint32_t stB  = stA + 16384;
        const uint32_t stBl = stA + 32768;

        #pragma unroll
        for (int kk = 0; kk < 4; kk++) {
            uint32_t fah[2][4], fal[2][4], fbh[2][4], fbl[2][4];
            #pragma unroll
            for (int i = 0; i < 2; i++) {
                int row = wm * 32 + i * 16 + aRow;
                int c16 = kk * 2 + aC;
                uint32_t phys = (uint32_t)(row * 128 + ((c16 ^ (row & 7)) << 4));
                ldm_x4(fah[i], stA  + phys);
                ldm_x4(fal[i], stAl + phys);
            }
            #pragma unroll
            for (int j = 0; j < 2; j++) {
                int row = wn * 32 + j * 16 + bRow;
                int c16 = kk * 2 + bC;
                uint32_t phys = (uint32_t)(row * 128 + ((c16 ^ (row & 7)) << 4));
                ldm_x4(fbh[j], stB  + phys);
                ldm_x4(fbl[j], stBl + phys);
            }
            #pragma unroll
            for (int i = 0; i < 2; i++)
                #pragma unroll
                for (int j = 0; j < 2; j++)
                    #pragma unroll
                    for (int jj = 0; jj < 2; jj++) {
                        float* a = acc[i][j * 2 + jj];
                        mma16816(a, fah[i], fbh[j] + jj * 2);
                        mma16816(a, fal[i], fbh[j] + jj * 2);
                        mma16816(a, fah[i], fbl[j] + jj * 2);
                    }
        }
        __syncthreads();

        if (kc + 2 < KC) {
            stage_load(kc + 2, s);
            asm volatile("cp.async.commit_group;" ::: "memory");
        }
    }

    #pragma unroll
    for (int i = 0; i < 2; i++) {
        int r0 = mBase + wm * 32 + i * 16 + g;
        #pragma unroll
        for (int j = 0; j < 4; j++) {
            int c = nBase + wn * 32 + j * 8 + 2 * tig;
            float b0 = bias ? bias[c]     : 0.f;
            float b1 = bias ? bias[c + 1] : 0.f;
            *(float2*)(C + (size_t)r0 * N + c) =
                make_float2(acc[i][j][0] + b0, acc[i][j][1] + b1);
            *(float2*)(C + (size_t)(r0 + 8) * N + c) =
                make_float2(acc[i][j][2] + b0, acc[i][j][3] + b1);
        }
    }
}

// ---------------- rotary + scale + scatter + bf16 hi/lo split ----------------
__global__ __launch_bounds__(256) void rotary_split_kernel(
    const float* __restrict__ qkv, const float* __restrict__ pos_emb,
    const float* __restrict__ scale,
    __nv_bfloat16* __restrict__ qh, __nv_bfloat16* __restrict__ ql,
    __nv_bfloat16* __restrict__ kh, __nv_bfloat16* __restrict__ kl,
    __nv_bfloat16* __restrict__ vh, __nv_bfloat16* __restrict__ vl)
{
    int idx = blockIdx.x * blockDim.x + threadIdx.x;
    if (idx >= MROWS * 384) return;
    int m = idx / 384;
    int p = idx - m * 384;
    int h = p >> 5;
    int t = p & 31;
    int i = m % NTOK;
    int b = m / NTOK;

    float sn = pos_emb[i * DHEAD + t];
    float cs = pos_emb[i * DHEAD + 32 + t];

    const float* row = qkv + (size_t)m * QKVCOLS;
    int col = h * DHEAD + 2 * t;
    float q0 = row[col],             q1 = row[col + 1];
    float k0 = row[INNER + col],     k1 = row[INNER + col + 1];
    float v0 = row[2 * INNER + col], v1 = row[2 * INNER + col + 1];
    float sc = scale[h];

    size_t dst = (((size_t)(b * HEADS + h)) * NTOK + i) * DHEAD + 2 * t;
    uint32_t hi, lo;
    split2((q0 * cs - q1 * sn) * sc, (q1 * cs + q0 * sn) * sc, hi, lo);
    *(uint32_t*)(qh + dst) = hi;
    *(uint32_t*)(ql + dst) = lo;
    split2(k0 * cs - k1 * sn, k1 * cs + k0 * sn, hi, lo);
    *(uint32_t*)(kh + dst) = hi;
    *(uint32_t*)(kl + dst) = lo;
    split2(v0, v1, hi, lo);
    *(uint32_t*)(vh + dst) = hi;
    *(uint32_t*)(vl + dst) = lo;
}

// ---------------- MMA attention v2: cp.async fill, SW128, no P arrays ------
// 224 threads = 7 warps; warp w owns query rows [w*32, w*32+32).
// smem (bytes): Qh 28K | Ql 28K | Kh 32K | Kl 32K | Vh 32K | Vl 32K = 184 KB
constexpr int SMQ  = 224 * 128;          // 28672
constexpr int SMKV = 256 * 128;          // 32768
constexpr int OFF_QH = 0;
constexpr int OFF_QL = SMQ;
constexpr int OFF_KH = 2 * SMQ;
constexpr int OFF_KL = 2 * SMQ + SMKV;
constexpr int OFF_VH = 2 * SMQ + 2 * SMKV;
constexpr int OFF_VL = 2 * SMQ + 3 * SMKV;
constexpr int ATT2_SMEM = 2 * SMQ + 4 * SMKV;   // 188416

__device__ __forceinline__ float maskv(float v, int r, int c) {
    if (c == r)     return MASK_FILL;
    if (c >= NTOK)  return -1e30f;
    return v;
}

__global__ __launch_bounds__(224, 1) void attention_mma2(
    const __nv_bfloat16* __restrict__ gqh, const __nv_bfloat16* __restrict__ gql,
    const __nv_bfloat16* __restrict__ gkh, const __nv_bfloat16* __restrict__ gkl,
    const __nv_bfloat16* __restrict__ gvh, const __nv_bfloat16* __restrict__ gvl,
    float* __restrict__ gout)
{
    extern __shared__ uint8_t dynsm[];
    const uint32_t sb = smem_u32(dynsm);

    const int bh   = blockIdx.x;
    const int b    = bh / HEADS;
    const int h    = bh - b * HEADS;
    const int tid  = threadIdx.x;
    const int w    = tid >> 5;
    const int lane = tid & 31;
    const int g    = lane >> 2;
    const int tig  = lane & 3;
    const size_t base = (size_t)bh * NTOK * DHEAD;

    // ---- async fill (zfill beyond NTOK rows) ----
    for (int i = tid; i < 224 * 8; i += 224) {       // Q: 8 iters
        int r = i >> 3, c = i & 7;
        uint32_t phys = (uint32_t)(r * 128 + ((c ^ (r & 7)) << 4));
        int vb = (r < NTOK) ? 16 : 0;
        size_t so = base + (size_t)(r < NTOK ? r : 0) * DHEAD + c * 8;
        cpa16z(sb + OFF_QH + phys, gqh + so, vb);
        cpa16z(sb + OFF_QL + phys, gql + so, vb);
    }
    for (int i = tid; i < 256 * 8; i += 224) {       // K,V: ~10 iters
        int r = i >> 3, c = i & 7;
        uint32_t phys = (uint32_t)(r * 128 + ((c ^ (r & 7)) << 4));
        int vb = (r < NTOK) ? 16 : 0;
        size_t so = base + (size_t)(r < NTOK ? r : 0) * DHEAD + c * 8;
        cpa16z(sb + OFF_KH + phys, gkh + so, vb);
        cpa16z(sb + OFF_KL + phys, gkl + so, vb);
        cpa16z(sb + OFF_VH + phys, gvh + so, vb);
        cpa16z(sb + OFF_VL + phys, gvl + so, vb);
    }
    asm volatile("cp.async.commit_group;" ::: "memory");
    asm volatile("cp.async.wait_group 0;" ::: "memory");
    __syncthreads();

    // per-lane ldmatrix row/col components
    const int qRO = (lane & 7) + ((lane & 8)  ? 8 : 0);   // A-frag / V-trans
    const int qC  = (lane & 16) ? 1 : 0;
    const int kRO = (lane & 7) + ((lane & 16) ? 8 : 0);   // B-frag
    const int kC  = (lane & 8)  ? 1 : 0;
    const int i0  = w * 32;

    float out[2][8][4];
    #pragma unroll
    for (int it = 0; it < 2; it++)
        #pragma unroll
        for (int jn = 0; jn < 8; jn++)
            #pragma unroll
            for (int r = 0; r < 4; r++) out[it][jn][r] = 0.f;

    float mrow[2][2] = {{-INFINITY, -INFINITY}, {-INFINITY, -INFINITY}};
    float rsum[2][2] = {{0.f, 0.f}, {0.f, 0.f}};

    for (int c = 0; c < 4; c++) {
        const int jc = c * 64;
        float s[2][8][4];
        #pragma unroll
        for (int it = 0; it < 2; it++)
            #pragma unroll
            for (int jn = 0; jn < 8; jn++)
                #pragma unroll
                for (int r = 0; r < 4; r++) s[it][jn][r] = 0.f;

        // ---- S = Q @ K^T ----
        #pragma unroll
        for (int kk = 0; kk < 4; kk++) {
            uint32_t qh[2][4], ql[2][4];
            #pragma unroll
            for (int it = 0; it < 2; it++) {
                int row = i0 + it * 16 + qRO;
                int c16 = kk * 2 + qC;
                uint32_t phys = (uint32_t)(row * 128 + ((c16 ^ (row & 7)) << 4));
                ldm_x4(qh[it], sb + OFF_QH + phys);
                ldm_x4(ql[it], sb + OFF_QL + phys);
            }
            #pragma unroll
            for (int np = 0; np < 4; np++) {
                uint32_t khf[4], klf[4];
                int row = jc + np * 16 + kRO;
                int c16 = kk * 2 + kC;
                uint32_t phys = (uint32_t)(row * 128 + ((c16 ^ (row & 7)) << 4));
                ldm_x4(khf, sb + OFF_KH + phys);
                ldm_x4(klf, sb + OFF_KL + phys);
                #pragma unroll
                for (int it = 0; it < 2; it++) {
                    mma16816(s[it][2 * np],     qh[it], khf);
                    mma16816(s[it][2 * np],     ql[it], khf);
                    mma16816(s[it][2 * np],     qh[it], klf);
                    mma16816(s[it][2 * np + 1], qh[it], khf + 2);
                    mma16816(s[it][2 * np + 1], ql[it], khf + 2);
                    mma16816(s[it][2 * np + 1], qh[it], klf + 2);
                }
            }
        }

        // ---- mask + online softmax ----
        float cm[2][2] = {{-INFINITY, -INFINITY}, {-INFINITY, -INFINITY}};
        #pragma unroll
        for (int it = 0; it < 2; it++) {
            int r0 = i0 + it * 16 + g;
            int r1 = r0 + 8;
            #pragma unroll
            for (int jn = 0; jn < 8; jn++) {
                int cb = jc + jn * 8 + 2 * tig;
                float* sv = s[it][jn];
                sv[0] = maskv(sv[0], r0, cb);
                sv[1] = maskv(sv[1], r0, cb + 1);
                sv[2] = maskv(sv[2], r1, cb);
                sv[3] = maskv(sv[3], r1, cb + 1);
                cm[it][0] = fmaxf(cm[it][0], fmaxf(sv[0], sv[1]));
                cm[it][1] = fmaxf(cm[it][1], fmaxf(sv[2], sv[3]));
            }
        }
        #pragma unroll
        for (int it = 0; it < 2; it++)
            #pragma unroll
            for (int hf = 0; hf < 2; hf++) {
                float v = cm[it][hf];
                v = fmaxf(v, __shfl_xor_sync(0xffffffffu, v, 1));
                v = fmaxf(v, __shfl_xor_sync(0xffffffffu, v, 2));
                float mnew = fmaxf(mrow[it][hf], v);
                float sc = __expf(mrow[it][hf] - mnew);
                mrow[it][hf] = mnew;
                rsum[it][hf] *= sc;
                #pragma unroll
                for (int jn = 0; jn < 8; jn++) {
                    out[it][jn][hf * 2]     *= sc;
                    out[it][jn][hf * 2 + 1] *= sc;
                }
            }
        #pragma unroll
        for (int it = 0; it < 2; it++) {
            float ls0 = 0.f, ls1 = 0.f;
            #pragma unroll
            for (int jn = 0; jn < 8; jn++) {
                float* sv = s[it][jn];
                sv[0] = __expf(sv[0] - mrow[it][0]);
                sv[1] = __expf(sv[1] - mrow[it][0]);
                sv[2] = __expf(sv[2] - mrow[it][1]);
                sv[3] = __expf(sv[3] - mrow[it][1]);
                ls0 += sv[0] + sv[1];
                ls1 += sv[2] + sv[3];
            }
            rsum[it][0] += ls0;
            rsum[it][1] += ls1;
        }

        // ---- out += P @ V (P split folded per-kk; no persistent arrays) ----
        #pragma unroll
        for (int kk = 0; kk < 4; kk++) {
            uint32_t pfh[2][4], pfl[2][4];
            #pragma unroll
            for (int it = 0; it < 2; it++) {
                split2(s[it][2 * kk][0],     s[it][2 * kk][1],
                       pfh[it][0], pfl[it][0]);
                split2(s[it][2 * kk][2],     s[it][2 * kk][3],
                       pfh[it][1], pfl[it][1]);
                split2(s[it][2 * kk + 1][0], s[it][2 * kk + 1][1],
                       pfh[it][2], pfl[it][2]);
                split2(s[it][2 * kk + 1][2], s[it][2 * kk + 1][3],
                       pfh[it][3], pfl[it][3]);
            }
            #pragma unroll
            for (int np = 0; np < 4; np++) {
                uint32_t vhf[4], vlf[4];
                int row = jc + kk * 16 + qRO;
                int c16 = np * 2 + qC;
                uint32_t phys = (uint32_t)(row * 128 + ((c16 ^ (row & 7)) << 4));
                ldm_x4_t(vhf, sb + OFF_VH + phys);
                ldm_x4_t(vlf, sb + OFF_VL + phys);
                #pragma unroll
                for (int it = 0; it < 2; it++) {
                    mma16816(out[it][2 * np],     pfh[it], vhf);
                    mma16816(out[it][2 * np],     pfl[it], vhf);
                    mma16816(out[it][2 * np],     pfh[it], vlf);
                    mma16816(out[it][2 * np + 1], pfh[it], vhf + 2);
                    mma16816(out[it][2 * np + 1], pfl[it], vhf + 2);
                    mma16816(out[it][2 * np + 1], pfh[it], vlf + 2);
                }
            }
        }
    }

    // ---- finalize ----
    #pragma unroll
    for (int it = 0; it < 2; it++) {
        float s0 = rsum[it][0];
        s0 += __shfl_xor_sync(0xffffffffu, s0, 1);
        s0 += __shfl_xor_sync(0xffffffffu, s0, 2);
        float s1 = rsum[it][1];
        s1 += __shfl_xor_sync(0xffffffffu, s1, 1);
        s1 += __shfl_xor_sync(0xffffffffu, s1, 2);
        float inv0 = 1.f / s0, inv1 = 1.f / s1;
        int r0 = i0 + it * 16 + g, r1 = r0 + 8;
        #pragma unroll
        for (int jn = 0; jn < 8; jn++) {
            int d = jn * 8 + 2 * tig;
            if (r0 < NTOK) {
                float2 v = make_float2(out[it][jn][0] * inv0,
                                       out[it][jn][1] * inv0);
                *(float2*)(gout + (size_t)(b * NTOK + r0) * INNER
                           + h * DHEAD + d) = v;
            }
            if (r1 < NTOK) {
                float2 v = make_float2(out[it][jn][2] * inv1,
                                       out[it][jn][3] * inv1);
                *(float2*)(gout + (size_t)(b * NTOK + r1) * INNER
                           + h * DHEAD + d) = v;
            }
        }
    }
}

// ---------------- launch ----------------
extern "C" void kernel_launch(void* const* d_in, const int* in_sizes, int n_in,
                              void* d_out, int out_size)
{
    const float* x       = (const float*)d_in[0];
    const float* pos_emb = (const float*)d_in[1];
    const float* w_qkv   = (const float*)d_in[2];
    const float* scale   = (const float*)d_in[3];
    const float* w_out   = (const float*)d_in[4];
    const float* b_out   = (const float*)d_in[5];
    float* out = (float*)d_out;

    float *qkv, *att;
    __nv_bfloat16 *ah, *al, *wqh, *wql, *woh, *wol;
    __nv_bfloat16 *qh, *ql, *kh, *kl, *vh, *vl;
    cudaGetSymbolAddress((void**)&qkv, g_qkv);
    cudaGetSymbolAddress((void**)&att, g_att);
    cudaGetSymbolAddress((void**)&ah,  g_Ah);
    cudaGetSymbolAddress((void**)&al,  g_Al);
    cudaGetSymbolAddress((void**)&wqh, g_Wqh);
    cudaGetSymbolAddress((void**)&wql, g_Wql);
    cudaGetSymbolAddress((void**)&woh, g_Woh);
    cudaGetSymbolAddress((void**)&wol, g_Wol);
    cudaGetSymbolAddress((void**)&qh,  g_qh);
    cudaGetSymbolAddress((void**)&ql,  g_ql);
    cudaGetSymbolAddress((void**)&kh,  g_kh);
    cudaGetSymbolAddress((void**)&kl,  g_kl);
    cudaGetSymbolAddress((void**)&vh,  g_vh);
    cudaGetSymbolAddress((void**)&vl,  g_vl);

    cudaFuncSetAttribute(attention_mma2,
                         cudaFuncAttributeMaxDynamicSharedMemorySize,
                         ATT2_SMEM);
    cudaFuncSetAttribute(gemm_bf16p,
                         cudaFuncAttributeMaxDynamicSharedMemorySize,
                         GEMM_SMEM);

    // 0) weights: transpose + split to bf16 hi/lo [N,K]
    transpose_split_kernel<<<dim3(QKVCOLS / 32, DIM / 32), dim3(32, 8)>>>(
        w_qkv, wqh, wql, DIM, QKVCOLS);
    transpose_split_kernel<<<dim3(DIM / 32, INNER / 32), dim3(32, 8)>>>(
        w_out, woh, wol, INNER, DIM);

    // 1) x -> bf16 hi/lo, then qkv = x @ w_qkv
    {
        int n4 = MROWS * DIM / 4;
        split_kernel<<<(n4 + 255) / 256, 256>>>(x, ah, al, n4);
    }
    gemm_bf16p<<<dim3(QKVCOLS / 128, MROWS / 64), 256, GEMM_SMEM>>>(
        ah, al, wqh, wql, nullptr, qkv, MROWS, QKVCOLS, DIM);

    // 2) rotary + scale + scatter + split
    {
        int total = MROWS * 384;
        rotary_split_kernel<<<(total + 255) / 256, 256>>>(
            qkv, pos_emb, scale, qh, ql, kh, kl, vh, vl);
    }

    // 3) attention (tensor-core, pre-split operands)
    attention_mma2<<<BATCH * HEADS, 224, ATT2_SMEM>>>(
        qh, ql, kh, kl, vh, vl, att);

    // 4) att -> bf16 hi/lo, then out = att @ w_out + b_out
    {
        int n4 = MROWS * INNER / 4;
        split_kernel<<<(n4 + 255) / 256, 256>>>(att, ah, al, n4);
    }
    gemm_bf16p<<<dim3(DIM / 128, MROWS / 64), 256, GEMM_SMEM>>>(
        ah, al, woh, wol, b_out, out, MROWS, DIM, INNER);
}

// round 11
// speedup vs baseline: 4.2772x; 1.3819x over previous
#include <cuda_runtime.h>
#include <cuda_fp16.h>
#include <cstdint>
#include <math.h>

// ---------------- problem constants ----------------
constexpr int BATCH   = 64;
constexpr int NTOK    = 197;
constexpr int DIM     = 768;
constexpr int HEADS   = 12;
constexpr int DHEAD   = 64;
constexpr int INNER   = HEADS * DHEAD;      // 768
constexpr int MROWS   = BATCH * NTOK;       // 12608 = 64 * 197
constexpr int QKVCOLS = 3 * INNER;          // 2304
constexpr int BHN     = BATCH * HEADS * NTOK * DHEAD;
constexpr float MASK_FILL = -987654321.0f;

// ---------------- scratch (device globals) ----------------
__device__ float g_qkv[(size_t)MROWS * QKVCOLS];
// fp16 split operands (activation side: hi+lo; weight/K/V side: hi only)
__device__ __align__(16) __half g_Ah[(size_t)MROWS * DIM];
__device__ __align__(16) __half g_Al[(size_t)MROWS * DIM];
__device__ __align__(16) __half g_Wqh[(size_t)QKVCOLS * DIM];
__device__ __align__(16) __half g_Woh[(size_t)DIM * INNER];
__device__ __align__(16) __half g_qh[BHN];
__device__ __align__(16) __half g_ql[BHN];
__device__ __align__(16) __half g_kh[BHN];
__device__ __align__(16) __half g_vh[BHN];

// ---------------- helpers ----------------
__device__ __forceinline__ void split2h(float x, float y,
                                        uint32_t& hi, uint32_t& lo) {
    __half hx = __float2half_rn(x);
    __half hy = __float2half_rn(y);
    __half2 hp;
    hp.x = hx; hp.y = hy;
    hi = *reinterpret_cast<uint32_t*>(&hp);
    __half2 lp;
    lp.x = __float2half_rn(x - __half2float(hx));
    lp.y = __float2half_rn(y - __half2float(hy));
    lo = *reinterpret_cast<uint32_t*>(&lp);
}

__device__ __forceinline__ uint32_t pack2h(float x, float y) {
    __half2 hp;
    hp.x = __float2half_rn(x);
    hp.y = __float2half_rn(y);
    return *reinterpret_cast<uint32_t*>(&hp);
}

__device__ __forceinline__ void mma16816(float* c, const uint32_t* a,
                                         const uint32_t* b) {
    asm volatile(
        "mma.sync.aligned.m16n8k16.row.col.f32.f16.f16.f32 "
        "{%0,%1,%2,%3}, {%4,%5,%6,%7}, {%8,%9}, {%0,%1,%2,%3};"
        : "+f"(c[0]), "+f"(c[1]), "+f"(c[2]), "+f"(c[3])
        : "r"(a[0]), "r"(a[1]), "r"(a[2]), "r"(a[3]),
          "r"(b[0]), "r"(b[1]));
}

__device__ __forceinline__ void ldm_x4(uint32_t* r, uint32_t addr) {
    asm volatile("ldmatrix.sync.aligned.m8n8.x4.shared.b16 {%0,%1,%2,%3}, [%4];"
        : "=r"(r[0]), "=r"(r[1]), "=r"(r[2]), "=r"(r[3]) : "r"(addr));
}

__device__ __forceinline__ void ldm_x4_t(uint32_t* r, uint32_t addr) {
    asm volatile("ldmatrix.sync.aligned.m8n8.x4.trans.shared.b16 {%0,%1,%2,%3}, [%4];"
        : "=r"(r[0]), "=r"(r[1]), "=r"(r[2]), "=r"(r[3]) : "r"(addr));
}

__device__ __forceinline__ uint32_t smem_u32(const void* p) {
    uint32_t a;
    asm("{ .reg .u64 t; cvta.to.shared.u64 t, %1; cvt.u32.u64 %0, t; }"
        : "=r"(a) : "l"(p));
    return a;
}

__device__ __forceinline__ void cpa16(uint32_t dst, const void* src) {
    asm volatile("cp.async.cg.shared.global [%0], [%1], 16;"
        :: "r"(dst), "l"(src));
}

__device__ __forceinline__ void cpa16z(uint32_t dst, const void* src, int vb) {
    asm volatile("cp.async.cg.shared.global [%0], [%1], 16, %2;"
        :: "r"(dst), "l"(src), "r"(vb));
}

// ---------------- pre-split kernels ----------------
// fp32 -> fp16 hi/lo, 4 elements per thread (activation side)
__global__ __launch_bounds__(256) void split_kernel(
    const float* __restrict__ src, __half* __restrict__ hi,
    __half* __restrict__ lo, int n4)
{
    int i = blockIdx.x * blockDim.x + threadIdx.x;
    if (i >= n4) return;
    float4 v = ((const float4*)src)[i];
    uint32_t h0, l0, h1, l1;
    split2h(v.x, v.y, h0, l0);
    split2h(v.z, v.w, h1, l1);
    ((uint2*)hi)[i] = make_uint2(h0, h1);
    ((uint2*)lo)[i] = make_uint2(l0, l1);
}

// transpose + fp16 quantize (weight side, hi only): [R][C] -> [C][R]
__global__ void transpose_half_kernel(
    const float* __restrict__ src, __half* __restrict__ dhi, int R, int C)
{
    __shared__ float t[32][33];
    int c0 = blockIdx.x * 32, r0 = blockIdx.y * 32;
    int x = threadIdx.x, y = threadIdx.y;   // (32, 8)
    #pragma unroll
    for (int i = 0; i < 32; i += 8)
        t[y + i][x] = src[(size_t)(r0 + y + i) * C + c0 + x];
    __syncthreads();
    #pragma unroll
    for (int i = 0; i < 32; i += 8)
        dhi[(size_t)(c0 + y + i) * R + r0 + x] = __float2half_rn(t[x][y + i]);
}

// ---------------- fp16 2-term GEMM ----------------
// C[M,N] = (Ah+Al)[M,K] @ Bh[N,K]^T (+bias); products: Ah*Bh + Al*Bh.
// CTA 64x128, k-chunk 64, 2-stage cp.async, SW128 rows (128B).
// stage: Ah 8K | Al 8K | Bh 16K = 32 KB; 2 stages = 64 KB -> 3 CTAs/SM.
constexpr int GSTAGE    = 32768;
constexpr int GEMM_SMEM = 2 * GSTAGE;    // 65536

__global__ __launch_bounds__(256) void gemm_f16p(
    const __half* __restrict__ Ah, const __half* __restrict__ Al,
    const __half* __restrict__ Bh,
    const float* __restrict__ bias, float* __restrict__ C,
    int M, int N, int K)
{
    extern __shared__ uint8_t dynsm[];
    const uint32_t sb = smem_u32(dynsm);
    const int tid  = threadIdx.x;
    const int lane = tid & 31;
    const int wid  = tid >> 5;
    const int g    = lane >> 2;
    const int tig  = lane & 3;
    const int wm   = wid & 1;
    const int wn   = wid >> 1;
    const int mBase = blockIdx.y * 64;
    const int nBase = blockIdx.x * 128;
    const int KC = K >> 6;

    const int aRow = lane & 15;
    const int aC   = lane >> 4;
    const int bRow = (lane & 7) + ((lane & 16) >> 1);
    const int bC   = (lane >> 3) & 1;

    float acc[2][4][4];
    #pragma unroll
    for (int i = 0; i < 2; i++)
        #pragma unroll
        for (int j = 0; j < 4; j++)
            #pragma unroll
            for (int r = 0; r < 4; r++) acc[i][j][r] = 0.f;

    auto stage_load = [&](int kc, int s) {
        const uint32_t st = sb + s * GSTAGE;
        #pragma unroll
        for (int p = 0; p < 2; p++) {       // A: 64 rows x 8 chunks (hi+lo)
            int idx = tid + p * 256;
            int r = idx >> 3, c = idx & 7;
            uint32_t phys = (uint32_t)(r * 128 + ((c ^ (r & 7)) << 4));
            size_t go = (size_t)(mBase + r) * K + kc * 64 + c * 8;
            cpa16(st + phys,        Ah + go);
            cpa16(st + 8192 + phys, Al + go);
        }
        #pragma unroll
        for (int p = 0; p < 4; p++) {       // B: 128 rows x 8 chunks (hi)
            int idx = tid + p * 256;
            int r = idx >> 3, c = idx & 7;
            uint32_t phys = (uint32_t)(r * 128 + ((c ^ (r & 7)) << 4));
            size_t go = (size_t)(nBase + r) * K + kc * 64 + c * 8;
            cpa16(st + 16384 + phys, Bh + go);
        }
    };

    stage_load(0, 0);
    asm volatile("cp.async.commit_group;" ::: "memory");
    if (KC > 1) {
        stage_load(1, 1);
        asm volatile("cp.async.commit_group;" ::: "memory");
    }

    for (int kc = 0; kc < KC; kc++) {
        const int s = kc & 1;
        if (kc == KC - 1)
            asm volatile("cp.async.wait_group 0;" ::: "memory");
        else
            asm volatile("cp.async.wait_group 1;" ::: "memory");
        __syncthreads();

        const uint32_t stA  = sb + s * GSTAGE;
        const uint32_t stAl = stA + 8192;
        const uint32_t stB  = stA + 16384;

        #pragma unroll
        for (int kk = 0; kk < 4; kk++) {
            uint32_t fah[2][4], fal[2][4], fbh[2][4];
            #pragma unroll
            for (int i = 0; i < 2; i++) {
                int row = wm * 32 + i * 16 + aRow;
                int c16 = kk * 2 + aC;
                uint32_t phys = (uint32_t)(row * 128 + ((c16 ^ (row & 7)) << 4));
                ldm_x4(fah[i], stA  + phys);
                ldm_x4(fal[i], stAl + phys);
            }
            #pragma unroll
            for (int j = 0; j < 2; j++) {
                int row = wn * 32 + j * 16 + bRow;
                int c16 = kk * 2 + bC;
                uint32_t phys = (uint32_t)(row * 128 + ((c16 ^ (row & 7)) << 4));
                ldm_x4(fbh[j], stB + phys);
            }
            #pragma unroll
            for (int i = 0; i < 2; i++)
                #pragma unroll
                for (int j = 0; j < 2; j++)
                    #pragma unroll
                    for (int jj = 0; jj < 2; jj++) {
                        float* a = acc[i][j * 2 + jj];
                        mma16816(a, fah[i], fbh[j] + jj * 2);
                        mma16816(a, fal[i], fbh[j] + jj * 2);
                    }
        }
        __syncthreads();

        if (kc + 2 < KC) {
            stage_load(kc + 2, s);
            asm volatile("cp.async.commit_group;" ::: "memory");
        }
    }

    #pragma unroll
    for (int i = 0; i < 2; i++) {
        int r0 = mBase + wm * 32 + i * 16 + g;
        #pragma unroll
        for (int j = 0; j < 4; j++) {
            int c = nBase + wn * 32 + j * 8 + 2 * tig;
            float b0 = bias ? bias[c]     : 0.f;
            float b1 = bias ? bias[c + 1] : 0.f;
            *(float2*)(C + (size_t)r0 * N + c) =
                make_float2(acc[i][j][0] + b0, acc[i][j][1] + b1);
            *(float2*)(C + (size_t)(r0 + 8) * N + c) =
                make_float2(acc[i][j][2] + b0, acc[i][j][3] + b1);
        }
    }
}

// ---------------- rotary + scale + scatter + fp16 split ----------------
// q: hi+lo (activation side); k, v: hi only (quantized side)
__global__ __launch_bounds__(256) void rotary_split_kernel(
    const float* __restrict__ qkv, const float* __restrict__ pos_emb,
    const float* __restrict__ scale,
    __half* __restrict__ qh, __half* __restrict__ ql,
    __half* __restrict__ kh, __half* __restrict__ vh)
{
    int idx = blockIdx.x * blockDim.x + threadIdx.x;
    if (idx >= MROWS * 384) return;
    int m = idx / 384;
    int p = idx - m * 384;
    int h = p >> 5;
    int t = p & 31;
    int i = m % NTOK;
    int b = m / NTOK;

    float sn = pos_emb[i * DHEAD + t];
    float cs = pos_emb[i * DHEAD + 32 + t];

    const float* row = qkv + (size_t)m * QKVCOLS;
    int col = h * DHEAD + 2 * t;
    float q0 = row[col],             q1 = row[col + 1];
    float k0 = row[INNER + col],     k1 = row[INNER + col + 1];
    float v0 = row[2 * INNER + col], v1 = row[2 * INNER + col + 1];
    float sc = scale[h];

    size_t dst = (((size_t)(b * HEADS + h)) * NTOK + i) * DHEAD + 2 * t;
    uint32_t hi, lo;
    split2h((q0 * cs - q1 * sn) * sc, (q1 * cs + q0 * sn) * sc, hi, lo);
    *(uint32_t*)(qh + dst) = hi;
    *(uint32_t*)(ql + dst) = lo;
    *(uint32_t*)(kh + dst) = pack2h(k0 * cs - k1 * sn, k1 * cs + k0 * sn);
    *(uint32_t*)(vh + dst) = pack2h(v0, v1);
}

// ---------------- MMA attention v3: fp16 2-term, direct split output ------
// 224 threads = 7 warps; warp w owns query rows [w*32, w*32+32).
// smem: Qh 28K | Ql 28K | Kh 32K | Vh 32K = 120 KB
constexpr int SMQ  = 224 * 128;
constexpr int SMKV = 256 * 128;
constexpr int OFF_QH = 0;
constexpr int OFF_QL = SMQ;
constexpr int OFF_KH = 2 * SMQ;
constexpr int OFF_VH = 2 * SMQ + SMKV;
constexpr int ATT3_SMEM = 2 * SMQ + 2 * SMKV;   // 122880

__device__ __forceinline__ float maskv(float v, int r, int c) {
    if (c == r)     return MASK_FILL;
    if (c >= NTOK)  return -1e30f;
    return v;
}

__global__ __launch_bounds__(224, 1) void attention_mma3(
    const __half* __restrict__ gqh, const __half* __restrict__ gql,
    const __half* __restrict__ gkh, const __half* __restrict__ gvh,
    __half* __restrict__ oh, __half* __restrict__ ol)
{
    extern __shared__ uint8_t dynsm[];
    const uint32_t sb = smem_u32(dynsm);

    const int bh   = blockIdx.x;
    const int b    = bh / HEADS;
    const int h    = bh - b * HEADS;
    const int tid  = threadIdx.x;
    const int w    = tid >> 5;
    const int lane = tid & 31;
    const int g    = lane >> 2;
    const int tig  = lane & 3;
    const size_t base = (size_t)bh * NTOK * DHEAD;

    // ---- async fill (zfill beyond NTOK rows) ----
    for (int i = tid; i < 224 * 8; i += 224) {       // Q hi+lo
        int r = i >> 3, c = i & 7;
        uint32_t phys = (uint32_t)(r * 128 + ((c ^ (r & 7)) << 4));
        int vb = (r < NTOK) ? 16 : 0;
        size_t so = base + (size_t)(r < NTOK ? r : 0) * DHEAD + c * 8;
        cpa16z(sb + OFF_QH + phys, gqh + so, vb);
        cpa16z(sb + OFF_QL + phys, gql + so, vb);
    }
    for (int i = tid; i < 256 * 8; i += 224) {       // K, V hi
        int r = i >> 3, c = i & 7;
        uint32_t phys = (uint32_t)(r * 128 + ((c ^ (r & 7)) << 4));
        int vb = (r < NTOK) ? 16 : 0;
        size_t so = base + (size_t)(r < NTOK ? r : 0) * DHEAD + c * 8;
        cpa16z(sb + OFF_KH + phys, gkh + so, vb);
        cpa16z(sb + OFF_VH + phys, gvh + so, vb);
    }
    asm volatile("cp.async.commit_group;" ::: "memory");
    asm volatile("cp.async.wait_group 0;" ::: "memory");
    __syncthreads();

    const int qRO = (lane & 7) + ((lane & 8)  ? 8 : 0);   // A-frag / V-trans
    const int qC  = (lane & 16) ? 1 : 0;
    const int kRO = (lane & 7) + ((lane & 16) ? 8 : 0);   // B-frag
    const int kC  = (lane & 8)  ? 1 : 0;
    const int i0  = w * 32;

    float out[2][8][4];
    #pragma unroll
    for (int it = 0; it < 2; it++)
        #pragma unroll
        for (int jn = 0; jn < 8; jn++)
            #pragma unroll
            for (int r = 0; r < 4; r++) out[it][jn][r] = 0.f;

    float mrow[2][2] = {{-INFINITY, -INFINITY}, {-INFINITY, -INFINITY}};
    float rsum[2][2] = {{0.f, 0.f}, {0.f, 0.f}};

    for (int c = 0; c < 4; c++) {
        const int jc = c * 64;
        float s[2][8][4];
        #pragma unroll
        for (int it = 0; it < 2; it++)
            #pragma unroll
            for (int jn = 0; jn < 8; jn++)
                #pragma unroll
                for (int r = 0; r < 4; r++) s[it][jn][r] = 0.f;

        // ---- S = (Qh+Ql) @ Kh^T ----
        #pragma unroll
        for (int kk = 0; kk < 4; kk++) {
            uint32_t qh[2][4], ql[2][4];
            #pragma unroll
            for (int it = 0; it < 2; it++) {
                int row = i0 + it * 16 + qRO;
                int c16 = kk * 2 + qC;
                uint32_t phys = (uint32_t)(row * 128 + ((c16 ^ (row & 7)) << 4));
                ldm_x4(qh[it], sb + OFF_QH + phys);
                ldm_x4(ql[it], sb + OFF_QL + phys);
            }
            #pragma unroll
            for (int np = 0; np < 4; np++) {
                uint32_t khf[4];
                int row = jc + np * 16 + kRO;
                int c16 = kk * 2 + kC;
                uint32_t phys = (uint32_t)(row * 128 + ((c16 ^ (row & 7)) << 4));
                ldm_x4(khf, sb + OFF_KH + phys);
                #pragma unroll
                for (int it = 0; it < 2; it++) {
                    mma16816(s[it][2 * np],     qh[it], khf);
                    mma16816(s[it][2 * np],     ql[it], khf);
                    mma16816(s[it][2 * np + 1], qh[it], khf + 2);
                    mma16816(s[it][2 * np + 1], ql[it], khf + 2);
                }
            }
        }

        // ---- mask + online softmax ----
        float cm[2][2] = {{-INFINITY, -INFINITY}, {-INFINITY, -INFINITY}};
        #pragma unroll
        for (int it = 0; it < 2; it++) {
            int r0 = i0 + it * 16 + g;
            int r1 = r0 + 8;
            #pragma unroll
            for (int jn = 0; jn < 8; jn++) {
                int cb = jc + jn * 8 + 2 * tig;
                float* sv = s[it][jn];
                sv[0] = maskv(sv[0], r0, cb);
                sv[1] = maskv(sv[1], r0, cb + 1);
                sv[2] = maskv(sv[2], r1, cb);
                sv[3] = maskv(sv[3], r1, cb + 1);
                cm[it][0] = fmaxf(cm[it][0], fmaxf(sv[0], sv[1]));
                cm[it][1] = fmaxf(cm[it][1], fmaxf(sv[2], sv[3]));
            }
        }
        #pragma unroll
        for (int it = 0; it < 2; it++)
            #pragma unroll
            for (int hf = 0; hf < 2; hf++) {
                float v = cm[it][hf];
                v = fmaxf(v, __shfl_xor_sync(0xffffffffu, v, 1));
                v = fmaxf(v, __shfl_xor_sync(0xffffffffu, v, 2));
                float mnew = fmaxf(mrow[it][hf], v);
                float sc = __expf(mrow[it][hf] - mnew);
                mrow[it][hf] = mnew;
                rsum[it][hf] *= sc;
                #pragma unroll
                for (int jn = 0; jn < 8; jn++) {
                    out[it][jn][hf * 2]     *= sc;
                    out[it][jn][hf * 2 + 1] *= sc;
                }
            }
        #pragma unroll
        for (int it = 0; it < 2; it++) {
            float ls0 = 0.f, ls1 = 0.f;
            #pragma unroll
            for (int jn = 0; jn < 8; jn++) {
                float* sv = s[it][jn];
                sv[0] = __expf(sv[0] - mrow[it][0]);
                sv[1] = __expf(sv[1] - mrow[it][0]);
                sv[2] = __expf(sv[2] - mrow[it][1]);
                sv[3] = __expf(sv[3] - mrow[it][1]);
                ls0 += sv[0] + sv[1];
                ls1 += sv[2] + sv[3];
            }
            rsum[it][0] += ls0;
            rsum[it][1] += ls1;
        }

        // ---- out += (Ph+Pl) @ Vh ----
        #pragma unroll
        for (int kk = 0; kk < 4; kk++) {
            uint32_t pfh[2][4], pfl[2][4];
            #pragma unroll
            for (int it = 0; it < 2; it++) {
                split2h(s[it][2 * kk][0],     s[it][2 * kk][1],
                        pfh[it][0], pfl[it][0]);
                split2h(s[it][2 * kk][2],     s[it][2 * kk][3],
                        pfh[it][1], pfl[it][1]);
                split2h(s[it][2 * kk + 1][0], s[it][2 * kk + 1][1],
                        pfh[it][2], pfl[it][2]);
                split2h(s[it][2 * kk + 1][2], s[it][2 * kk + 1][3],
                        pfh[it][3], pfl[it][3]);
            }
            #pragma unroll
            for (int np = 0; np < 4; np++) {
                uint32_t vhf[4];
                int row = jc + kk * 16 + qRO;
                int c16 = np * 2 + qC;
                uint32_t phys = (uint32_t)(row * 128 + ((c16 ^ (row & 7)) << 4));
                ldm_x4_t(vhf, sb + OFF_VH + phys);
                #pragma unroll
                for (int it = 0; it < 2; it++) {
                    mma16816(out[it][2 * np],     pfh[it], vhf);
                    mma16816(out[it][2 * np],     pfl[it], vhf);
                    mma16816(out[it][2 * np + 1], pfh[it], vhf + 2);
                    mma16816(out[it][2 * np + 1], pfl[it], vhf + 2);
                }
            }
        }
    }

    // ---- finalize: normalize, split fp16 hi/lo, write ----
    #pragma unroll
    for (int it = 0; it < 2; it++) {
        float s0 = rsum[it][0];
        s0 += __shfl_xor_sync(0xffffffffu, s0, 1);
        s0 += __shfl_xor_sync(0xffffffffu, s0, 2);
        float s1 = rsum[it][1];
        s1 += __shfl_xor_sync(0xffffffffu, s1, 1);
        s1 += __shfl_xor_sync(0xffffffffu, s1, 2);
        float inv0 = 1.f / s0, inv1 = 1.f / s1;
        int r0 = i0 + it * 16 + g, r1 = r0 + 8;
        #pragma unroll
        for (int jn = 0; jn < 8; jn++) {
            int d = jn * 8 + 2 * tig;
            uint32_t hi, lo;
            if (r0 < NTOK) {
                size_t e = (size_t)(b * NTOK + r0) * INNER + h * DHEAD + d;
                split2h(out[it][jn][0] * inv0, out[it][jn][1] * inv0, hi, lo);
                *(uint32_t*)(oh + e) = hi;
                *(uint32_t*)(ol + e) = lo;
            }
            if (r1 < NTOK) {
                size_t e = (size_t)(b * NTOK + r1) * INNER + h * DHEAD + d;
                split2h(out[it][jn][2] * inv1, out[it][jn][3] * inv1, hi, lo);
                *(uint32_t*)(oh + e) = hi;
                *(uint32_t*)(ol + e) = lo;
            }
        }
    }
}

// ---------------- launch ----------------
extern "C" void kernel_launch(void* const* d_in, const int* in_sizes, int n_in,
                              void* d_out, int out_size)
{
    const float* x       = (const float*)d_in[0];
    const float* pos_emb = (const float*)d_in[1];
    const float* w_qkv   = (const float*)d_in[2];
    const float* scale   = (const float*)d_in[3];
    const float* w_out   = (const float*)d_in[4];
    const float* b_out   = (const float*)d_in[5];
    float* out = (float*)d_out;

    float* qkv;
    __half *ah, *al, *wqh, *woh, *qh, *ql, *kh, *vh;
    cudaGetSymbolAddress((void**)&qkv, g_qkv);
    cudaGetSymbolAddress((void**)&ah,  g_Ah);
    cudaGetSymbolAddress((void**)&al,  g_Al);
    cudaGetSymbolAddress((void**)&wqh, g_Wqh);
    cudaGetSymbolAddress((void**)&woh, g_Woh);
    cudaGetSymbolAddress((void**)&qh,  g_qh);
    cudaGetSymbolAddress((void**)&ql,  g_ql);
    cudaGetSymbolAddress((void**)&kh,  g_kh);
    cudaGetSymbolAddress((void**)&vh,  g_vh);

    cudaFuncSetAttribute(attention_mma3,
                         cudaFuncAttributeMaxDynamicSharedMemorySize,
                         ATT3_SMEM);
    cudaFuncSetAttribute(gemm_f16p,
                         cudaFuncAttributeMaxDynamicSharedMemorySize,
                         GEMM_SMEM);

    // 0) weights: transpose + fp16 quantize [N,K]
    transpose_half_kernel<<<dim3(QKVCOLS / 32, DIM / 32), dim3(32, 8)>>>(
        w_qkv, wqh, DIM, QKVCOLS);
    transpose_half_kernel<<<dim3(DIM / 32, INNER / 32), dim3(32, 8)>>>(
        w_out, woh, INNER, DIM);

    // 1) x -> fp16 hi/lo, then qkv = x @ w_qkv
    {
        int n4 = MROWS * DIM / 4;
        split_kernel<<<(n4 + 255) / 256, 256>>>(x, ah, al, n4);
    }
    gemm_f16p<<<dim3(QKVCOLS / 128, MROWS / 64), 256, GEMM_SMEM>>>(
        ah, al, wqh, nullptr, qkv, MROWS, QKVCOLS, DIM);

    // 2) rotary + scale + scatter + split
    {
        int total = MROWS * 384;
        rotary_split_kernel<<<(total + 255) / 256, 256>>>(
            qkv, pos_emb, scale, qh, ql, kh, vh);
    }

    // 3) attention (fp16 tensor-core, writes split output for out-proj)
    attention_mma3<<<BATCH * HEADS, 224, ATT3_SMEM>>>(
        qh, ql, kh, vh, ah, al);

    // 4) out = att @ w_out + b_out
    gemm_f16p<<<dim3(DIM / 128, MROWS / 64), 256, GEMM_SMEM>>>(
        ah, al, woh, b_out, out, MROWS, DIM, INNER);
}

// round 13
// speedup vs baseline: 4.5232x; 1.0575x over previous
#include <cuda_runtime.h>
#include <cuda_fp16.h>
#include <cstdint>
#include <math.h>

// ---------------- problem constants ----------------
constexpr int BATCH   = 64;
constexpr int NTOK    = 197;
constexpr int DIM     = 768;
constexpr int HEADS   = 12;
constexpr int DHEAD   = 64;
constexpr int INNER   = HEADS * DHEAD;      // 768
constexpr int MROWS   = BATCH * NTOK;       // 12608 = 64 * 197
constexpr int QKVCOLS = 3 * INNER;          // 2304
constexpr int BHN     = BATCH * HEADS * NTOK * DHEAD;
constexpr float MASK_FILL = -987654321.0f;

// ---------------- scratch (device globals) ----------------
// fp16 split operands (activation side: hi+lo; weight/K/V side: hi only)
__device__ __align__(16) __half g_Ah[(size_t)MROWS * DIM];
__device__ __align__(16) __half g_Al[(size_t)MROWS * DIM];
__device__ __align__(16) __half g_Wqh[(size_t)QKVCOLS * DIM];
__device__ __align__(16) __half g_Woh[(size_t)DIM * INNER];
__device__ __align__(16) __half g_qh[BHN];
__device__ __align__(16) __half g_ql[BHN];
__device__ __align__(16) __half g_kh[BHN];
__device__ __align__(16) __half g_vh[BHN];

// ---------------- helpers ----------------
__device__ __forceinline__ void split2h(float x, float y,
                                        uint32_t& hi, uint32_t& lo) {
    __half hx = __float2half_rn(x);
    __half hy = __float2half_rn(y);
    __half2 hp;
    hp.x = hx; hp.y = hy;
    hi = *reinterpret_cast<uint32_t*>(&hp);
    __half2 lp;
    lp.x = __float2half_rn(x - __half2float(hx));
    lp.y = __float2half_rn(y - __half2float(hy));
    lo = *reinterpret_cast<uint32_t*>(&lp);
}

__device__ __forceinline__ uint32_t pack2h(float x, float y) {
    __half2 hp;
    hp.x = __float2half_rn(x);
    hp.y = __float2half_rn(y);
    return *reinterpret_cast<uint32_t*>(&hp);
}

__device__ __forceinline__ void mma16816(float* c, const uint32_t* a,
                                         const uint32_t* b) {
    asm volatile(
        "mma.sync.aligned.m16n8k16.row.col.f32.f16.f16.f32 "
        "{%0,%1,%2,%3}, {%4,%5,%6,%7}, {%8,%9}, {%0,%1,%2,%3};"
        : "+f"(c[0]), "+f"(c[1]), "+f"(c[2]), "+f"(c[3])
        : "r"(a[0]), "r"(a[1]), "r"(a[2]), "r"(a[3]),
          "r"(b[0]), "r"(b[1]));
}

__device__ __forceinline__ void ldm_x4(uint32_t* r, uint32_t addr) {
    asm volatile("ldmatrix.sync.aligned.m8n8.x4.shared.b16 {%0,%1,%2,%3}, [%4];"
        : "=r"(r[0]), "=r"(r[1]), "=r"(r[2]), "=r"(r[3]) : "r"(addr));
}

__device__ __forceinline__ void ldm_x4_t(uint32_t* r, uint32_t addr) {
    asm volatile("ldmatrix.sync.aligned.m8n8.x4.trans.shared.b16 {%0,%1,%2,%3}, [%4];"
        : "=r"(r[0]), "=r"(r[1]), "=r"(r[2]), "=r"(r[3]) : "r"(addr));
}

__device__ __forceinline__ uint32_t smem_u32(const void* p) {
    uint32_t a;
    asm("{ .reg .u64 t; cvta.to.shared.u64 t, %1; cvt.u32.u64 %0, t; }"
        : "=r"(a) : "l"(p));
    return a;
}

__device__ __forceinline__ void cpa16(uint32_t dst, const void* src) {
    asm volatile("cp.async.cg.shared.global [%0], [%1], 16;"
        :: "r"(dst), "l"(src));
}

__device__ __forceinline__ void cpa16z(uint32_t dst, const void* src, int vb) {
    asm volatile("cp.async.cg.shared.global [%0], [%1], 16, %2;"
        :: "r"(dst), "l"(src), "r"(vb));
}

// ---------------- pre-split kernels ----------------
__global__ __launch_bounds__(256) void split_kernel(
    const float* __restrict__ src, __half* __restrict__ hi,
    __half* __restrict__ lo, int n4)
{
    int i = blockIdx.x * blockDim.x + threadIdx.x;
    if (i >= n4) return;
    float4 v = ((const float4*)src)[i];
    uint32_t h0, l0, h1, l1;
    split2h(v.x, v.y, h0, l0);
    split2h(v.z, v.w, h1, l1);
    ((uint2*)hi)[i] = make_uint2(h0, h1);
    ((uint2*)lo)[i] = make_uint2(l0, l1);
}

__global__ void transpose_half_kernel(
    const float* __restrict__ src, __half* __restrict__ dhi, int R, int C)
{
    __shared__ float t[32][33];
    int c0 = blockIdx.x * 32, r0 = blockIdx.y * 32;
    int x = threadIdx.x, y = threadIdx.y;   // (32, 8)
    #pragma unroll
    for (int i = 0; i < 32; i += 8)
        t[y + i][x] = src[(size_t)(r0 + y + i) * C + c0 + x];
    __syncthreads();
    #pragma unroll
    for (int i = 0; i < 32; i += 8)
        dhi[(size_t)(c0 + y + i) * R + r0 + x] = __float2half_rn(t[x][y + i]);
}

// ---------------- shared GEMM mainloop ----------------
// Computes acc[2][4][4] for CTA tile 64x128, k-chunk 64, 2-stage cp.async.
constexpr int GSTAGE    = 32768;
constexpr int GEMM_SMEM = 2 * GSTAGE;    // 65536 -> 3 CTAs/SM

struct GemmCtx {
    int tid, lane, wid, g, tig, wm, wn, mBase, nBase;
};

__device__ __forceinline__ void gemm_mainloop(
    const __half* __restrict__ Ah, const __half* __restrict__ Al,
    const __half* __restrict__ Bh, int K, const GemmCtx& cx,
    uint32_t sb, float acc[2][4][4])
{
    const int KC = K >> 6;
    const int aRow = cx.lane & 15;
    const int aC   = cx.lane >> 4;
    const int bRow = (cx.lane & 7) + ((cx.lane & 16) >> 1);
    const int bC   = (cx.lane >> 3) & 1;

    #pragma unroll
    for (int i = 0; i < 2; i++)
        #pragma unroll
        for (int j = 0; j < 4; j++)
            #pragma unroll
            for (int r = 0; r < 4; r++) acc[i][j][r] = 0.f;

    auto stage_load = [&](int kc, int s) {
        const uint32_t st = sb + s * GSTAGE;
        #pragma unroll
        for (int p = 0; p < 2; p++) {
            int idx = cx.tid + p * 256;
            int r = idx >> 3, c = idx & 7;
            uint32_t phys = (uint32_t)(r * 128 + ((c ^ (r & 7)) << 4));
            size_t go = (size_t)(cx.mBase + r) * K + kc * 64 + c * 8;
            cpa16(st + phys,        Ah + go);
            cpa16(st + 8192 + phys, Al + go);
        }
        #pragma unroll
        for (int p = 0; p < 4; p++) {
            int idx = cx.tid + p * 256;
            int r = idx >> 3, c = idx & 7;
            uint32_t phys = (uint32_t)(r * 128 + ((c ^ (r & 7)) << 4));
            size_t go = (size_t)(cx.nBase + r) * K + kc * 64 + c * 8;
            cpa16(st + 16384 + phys, Bh + go);
        }
    };

    stage_load(0, 0);
    asm volatile("cp.async.commit_group;" ::: "memory");
    if (KC > 1) {
        stage_load(1, 1);
        asm volatile("cp.async.commit_group;" ::: "memory");
    }

    for (int kc = 0; kc < KC; kc++) {
        const int s = kc & 1;
        if (kc == KC - 1)
            asm volatile("cp.async.wait_group 0;" ::: "memory");
        else
            asm volatile("cp.async.wait_group 1;" ::: "memory");
        __syncthreads();

        const uint32_t stA  = sb + s * GSTAGE;
        const uint32_t stAl = stA + 8192;
        const uint32_t stB  = stA + 16384;

        #pragma unroll
        for (int kk = 0; kk < 4; kk++) {
            uint32_t fah[2][4], fal[2][4], fbh[2][4];
            #pragma unroll
            for (int i = 0; i < 2; i++) {
                int row = cx.wm * 32 + i * 16 + aRow;
                int c16 = kk * 2 + aC;
                uint32_t phys = (uint32_t)(row * 128 + ((c16 ^ (row & 7)) << 4));
                ldm_x4(fah[i], stA  + phys);
                ldm_x4(fal[i], stAl + phys);
            }
            #pragma unroll
            for (int j = 0; j < 2; j++) {
                int row = cx.wn * 32 + j * 16 + bRow;
                int c16 = kk * 2 + bC;
                uint32_t phys = (uint32_t)(row * 128 + ((c16 ^ (row & 7)) << 4));
                ldm_x4(fbh[j], stB + phys);
            }
            #pragma unroll
            for (int i = 0; i < 2; i++)
                #pragma unroll
                for (int j = 0; j < 2; j++)
                    #pragma unroll
                    for (int jj = 0; jj < 2; jj++) {
                        float* a = acc[i][j * 2 + jj];
                        mma16816(a, fah[i], fbh[j] + jj * 2);
                        mma16816(a, fal[i], fbh[j] + jj * 2);
                    }
        }
        __syncthreads();

        if (kc + 2 < KC) {
            stage_load(kc + 2, s);
            asm volatile("cp.async.commit_group;" ::: "memory");
        }
    }
}

__device__ __forceinline__ GemmCtx make_ctx() {
    GemmCtx cx;
    cx.tid  = threadIdx.x;
    cx.lane = cx.tid & 31;
    cx.wid  = cx.tid >> 5;
    cx.g    = cx.lane >> 2;
    cx.tig  = cx.lane & 3;
    cx.wm   = cx.wid & 1;
    cx.wn   = cx.wid >> 1;
    cx.mBase = blockIdx.y * 64;
    cx.nBase = blockIdx.x * 128;
    return cx;
}

// ---------------- qkv GEMM with fused rotary+scale+scatter+split --------
__global__ __launch_bounds__(256) void gemm_qkv_rot(
    const __half* __restrict__ Ah, const __half* __restrict__ Al,
    const __half* __restrict__ Bh,
    const float* __restrict__ pos_emb, const float* __restrict__ scale,
    __half* __restrict__ qh, __half* __restrict__ ql,
    __half* __restrict__ kh, __half* __restrict__ vh)
{
    extern __shared__ uint8_t dynsm[];
    const uint32_t sb = smem_u32(dynsm);
    GemmCtx cx = make_ctx();
    float acc[2][4][4];
    gemm_mainloop(Ah, Al, Bh, DIM, cx, sb, acc);

    // fused epilogue: rotary + scale + scatter + fp16 split
    #pragma unroll
    for (int i = 0; i < 2; i++) {
        int gr0 = cx.mBase + cx.wm * 32 + i * 16 + cx.g;
        #pragma unroll
        for (int j = 0; j < 4; j++) {
            int col = cx.nBase + cx.wn * 32 + j * 8 + 2 * cx.tig;
            int sec = col / INNER;             // 0=q 1=k 2=v
            int cc  = col - sec * INNER;
            int h   = cc >> 6;
            int t   = (cc & 63) >> 1;
            #pragma unroll
            for (int rr = 0; rr < 2; rr++) {
                int m  = gr0 + rr * 8;
                int bb = m / NTOK;
                int ib = m - bb * NTOK;
                float v0 = acc[i][j][rr * 2];
                float v1 = acc[i][j][rr * 2 + 1];
                size_t dst = (((size_t)(bb * HEADS + h)) * NTOK + ib) * DHEAD
                             + 2 * t;
                if (sec == 2) {
                    *(uint32_t*)(vh + dst) = pack2h(v0, v1);
                } else {
                    float sn = pos_emb[ib * DHEAD + t];
                    float cs = pos_emb[ib * DHEAD + 32 + t];
                    float r0 = v0 * cs - v1 * sn;
                    float r1 = v1 * cs + v0 * sn;
                    if (sec == 0) {
                        float sc = scale[h];
                        uint32_t hi, lo;
                        split2h(r0 * sc, r1 * sc, hi, lo);
                        *(uint32_t*)(qh + dst) = hi;
                        *(uint32_t*)(ql + dst) = lo;
                    } else {
                        *(uint32_t*)(kh + dst) = pack2h(r0, r1);
                    }
                }
            }
        }
    }
}

// ---------------- plain fp16 2-term GEMM (out projection) ----------------
__global__ __launch_bounds__(256) void gemm_f16p(
    const __half* __restrict__ Ah, const __half* __restrict__ Al,
    const __half* __restrict__ Bh,
    const float* __restrict__ bias, float* __restrict__ C,
    int M, int N, int K)
{
    extern __shared__ uint8_t dynsm[];
    const uint32_t sb = smem_u32(dynsm);
    GemmCtx cx = make_ctx();
    float acc[2][4][4];
    gemm_mainloop(Ah, Al, Bh, K, cx, sb, acc);

    #pragma unroll
    for (int i = 0; i < 2; i++) {
        int r0 = cx.mBase + cx.wm * 32 + i * 16 + cx.g;
        #pragma unroll
        for (int j = 0; j < 4; j++) {
            int c = cx.nBase + cx.wn * 32 + j * 8 + 2 * cx.tig;
            float b0 = bias ? bias[c]     : 0.f;
            float b1 = bias ? bias[c + 1] : 0.f;
            *(float2*)(C + (size_t)r0 * N + c) =
                make_float2(acc[i][j][0] + b0, acc[i][j][1] + b1);
            *(float2*)(C + (size_t)(r0 + 8) * N + c) =
                make_float2(acc[i][j][2] + b0, acc[i][j][3] + b1);
        }
    }
}

// ---------------- MMA attention v3 ----------------
constexpr int SMQ  = 224 * 128;
constexpr int SMKV = 256 * 128;
constexpr int OFF_QH = 0;
constexpr int OFF_QL = SMQ;
constexpr int OFF_KH = 2 * SMQ;
constexpr int OFF_VH = 2 * SMQ + SMKV;
constexpr int ATT3_SMEM = 2 * SMQ + 2 * SMKV;   // 122880

__device__ __forceinline__ float maskv(float v, int r, int c) {
    if (c == r)     return MASK_FILL;
    if (c >= NTOK)  return -1e30f;
    return v;
}

__global__ __launch_bounds__(224, 1) void attention_mma3(
    const __half* __restrict__ gqh, const __half* __restrict__ gql,
    const __half* __restrict__ gkh, const __half* __restrict__ gvh,
    __half* __restrict__ oh, __half* __restrict__ ol)
{
    extern __shared__ uint8_t dynsm[];
    const uint32_t sb = smem_u32(dynsm);

    const int bh   = blockIdx.x;
    const int b    = bh / HEADS;
    const int h    = bh - b * HEADS;
    const int tid  = threadIdx.x;
    const int w    = tid >> 5;
    const int lane = tid & 31;
    const int g    = lane >> 2;
    const int tig  = lane & 3;
    const size_t base = (size_t)bh * NTOK * DHEAD;

    for (int i = tid; i < 224 * 8; i += 224) {
        int r = i >> 3, c = i & 7;
        uint32_t phys = (uint32_t)(r * 128 + ((c ^ (r & 7)) << 4));
        int vb = (r < NTOK) ? 16 : 0;
        size_t so = base + (size_t)(r < NTOK ? r : 0) * DHEAD + c * 8;
        cpa16z(sb + OFF_QH + phys, gqh + so, vb);
        cpa16z(sb + OFF_QL + phys, gql + so, vb);
    }
    for (int i = tid; i < 256 * 8; i += 224) {
        int r = i >> 3, c = i & 7;
        uint32_t phys = (uint32_t)(r * 128 + ((c ^ (r & 7)) << 4));
        int vb = (r < NTOK) ? 16 : 0;
        size_t so = base + (size_t)(r < NTOK ? r : 0) * DHEAD + c * 8;
        cpa16z(sb + OFF_KH + phys, gkh + so, vb);
        cpa16z(sb + OFF_VH + phys, gvh + so, vb);
    }
    asm volatile("cp.async.commit_group;" ::: "memory");
    asm volatile("cp.async.wait_group 0;" ::: "memory");
    __syncthreads();

    const int qRO = (lane & 7) + ((lane & 8)  ? 8 : 0);
    const int qC  = (lane & 16) ? 1 : 0;
    const int kRO = (lane & 7) + ((lane & 16) ? 8 : 0);
    const int kC  = (lane & 8)  ? 1 : 0;
    const int i0  = w * 32;

    float out[2][8][4];
    #pragma unroll
    for (int it = 0; it < 2; it++)
        #pragma unroll
        for (int jn = 0; jn < 8; jn++)
            #pragma unroll
            for (int r = 0; r < 4; r++) out[it][jn][r] = 0.f;

    float mrow[2][2] = {{-INFINITY, -INFINITY}, {-INFINITY, -INFINITY}};
    float rsum[2][2] = {{0.f, 0.f}, {0.f, 0.f}};

    for (int c = 0; c < 4; c++) {
        const int jc = c * 64;
        float s[2][8][4];
        #pragma unroll
        for (int it = 0; it < 2; it++)
            #pragma unroll
            for (int jn = 0; jn < 8; jn++)
                #pragma unroll
                for (int r = 0; r < 4; r++) s[it][jn][r] = 0.f;

        #pragma unroll
        for (int kk = 0; kk < 4; kk++) {
            uint32_t qh[2][4], ql[2][4];
            #pragma unroll
            for (int it = 0; it < 2; it++) {
                int row = i0 + it * 16 + qRO;
                int c16 = kk * 2 + qC;
                uint32_t phys = (uint32_t)(row * 128 + ((c16 ^ (row & 7)) << 4));
                ldm_x4(qh[it], sb + OFF_QH + phys);
                ldm_x4(ql[it], sb + OFF_QL + phys);
            }
            #pragma unroll
            for (int np = 0; np < 4; np++) {
                uint32_t khf[4];
                int row = jc + np * 16 + kRO;
                int c16 = kk * 2 + kC;
                uint32_t phys = (uint32_t)(row * 128 + ((c16 ^ (row & 7)) << 4));
                ldm_x4(khf, sb + OFF_KH + phys);
                #pragma unroll
                for (int it = 0; it < 2; it++) {
                    mma16816(s[it][2 * np],     qh[it], khf);
                    mma16816(s[it][2 * np],     ql[it], khf);
                    mma16816(s[it][2 * np + 1], qh[it], khf + 2);
                    mma16816(s[it][2 * np + 1], ql[it], khf + 2);
                }
            }
        }

        float cm[2][2] = {{-INFINITY, -INFINITY}, {-INFINITY, -INFINITY}};
        #pragma unroll
        for (int it = 0; it < 2; it++) {
            int r0 = i0 + it * 16 + g;
            int r1 = r0 + 8;
            #pragma unroll
            for (int jn = 0; jn < 8; jn++) {
                int cb = jc + jn * 8 + 2 * tig;
                float* sv = s[it][jn];
                sv[0] = maskv(sv[0], r0, cb);
                sv[1] = maskv(sv[1], r0, cb + 1);
                sv[2] = maskv(sv[2], r1, cb);
                sv[3] = maskv(sv[3], r1, cb + 1);
                cm[it][0] = fmaxf(cm[it][0], fmaxf(sv[0], sv[1]));
                cm[it][1] = fmaxf(cm[it][1], fmaxf(sv[2], sv[3]));
            }
        }
        #pragma unroll
        for (int it = 0; it < 2; it++)
            #pragma unroll
            for (int hf = 0; hf < 2; hf++) {
                float v = cm[it][hf];
                v = fmaxf(v, __shfl_xor_sync(0xffffffffu, v, 1));
                v = fmaxf(v, __shfl_xor_sync(0xffffffffu, v, 2));
                float mnew = fmaxf(mrow[it][hf], v);
                float sc = __expf(mrow[it][hf] - mnew);
                mrow[it][hf] = mnew;
                rsum[it][hf] *= sc;
                #pragma unroll
                for (int jn = 0; jn < 8; jn++) {
                    out[it][jn][hf * 2]     *= sc;
                    out[it][jn][hf * 2 + 1] *= sc;
                }
            }
        #pragma unroll
        for (int it = 0; it < 2; it++) {
            float ls0 = 0.f, ls1 = 0.f;
            #pragma unroll
            for (int jn = 0; jn < 8; jn++) {
                float* sv = s[it][jn];
                sv[0] = __expf(sv[0] - mrow[it][0]);
                sv[1] = __expf(sv[1] - mrow[it][0]);
                sv[2] = __expf(sv[2] - mrow[it][1]);
                sv[3] = __expf(sv[3] - mrow[it][1]);
                ls0 += sv[0] + sv[1];
                ls1 += sv[2] + sv[3];
            }
            rsum[it][0] += ls0;
            rsum[it][1] += ls1;
        }

        #pragma unroll
        for (int kk = 0; kk < 4; kk++) {
            uint32_t pfh[2][4], pfl[2][4];
            #pragma unroll
            for (int it = 0; it < 2; it++) {
                split2h(s[it][2 * kk][0],     s[it][2 * kk][1],
                        pfh[it][0], pfl[it][0]);
                split2h(s[it][2 * kk][2],     s[it][2 * kk][3],
                        pfh[it][1], pfl[it][1]);
                split2h(s[it][2 * kk + 1][0], s[it][2 * kk + 1][1],
                        pfh[it][2], pfl[it][2]);
                split2h(s[it][2 * kk + 1][2], s[it][2 * kk + 1][3],
                        pfh[it][3], pfl[it][3]);
            }
            #pragma unroll
            for (int np = 0; np < 4; np++) {
                uint32_t vhf[4];
                int row = jc + kk * 16 + qRO;
                int c16 = np * 2 + qC;
                uint32_t phys = (uint32_t)(row * 128 + ((c16 ^ (row & 7)) << 4));
                ldm_x4_t(vhf, sb + OFF_VH + phys);
                #pragma unroll
                for (int it = 0; it < 2; it++) {
                    mma16816(out[it][2 * np],     pfh[it], vhf);
                    mma16816(out[it][2 * np],     pfl[it], vhf);
                    mma16816(out[it][2 * np + 1], pfh[it], vhf + 2);
                    mma16816(out[it][2 * np + 1], pfl[it], vhf + 2);
                }
            }
        }
    }

    #pragma unroll
    for (int it = 0; it < 2; it++) {
        float s0 = rsum[it][0];
        s0 += __shfl_xor_sync(0xffffffffu, s0, 1);
        s0 += __shfl_xor_sync(0xffffffffu, s0, 2);
        float s1 = rsum[it][1];
        s1 += __shfl_xor_sync(0xffffffffu, s1, 1);
        s1 += __shfl_xor_sync(0xffffffffu, s1, 2);
        float inv0 = 1.f / s0, inv1 = 1.f / s1;
        int r0 = i0 + it * 16 + g, r1 = r0 + 8;
        #pragma unroll
        for (int jn = 0; jn < 8; jn++) {
            int d = jn * 8 + 2 * tig;
            uint32_t hi, lo;
            if (r0 < NTOK) {
                size_t e = (size_t)(b * NTOK + r0) * INNER + h * DHEAD + d;
                split2h(out[it][jn][0] * inv0, out[it][jn][1] * inv0, hi, lo);
                *(uint32_t*)(oh + e) = hi;
                *(uint32_t*)(ol + e) = lo;
            }
            if (r1 < NTOK) {
                size_t e = (size_t)(b * NTOK + r1) * INNER + h * DHEAD + d;
                split2h(out[it][jn][2] * inv1, out[it][jn][3] * inv1, hi, lo);
                *(uint32_t*)(oh + e) = hi;
                *(uint32_t*)(ol + e) = lo;
            }
        }
    }
}

// ---------------- launch ----------------
extern "C" void kernel_launch(void* const* d_in, const int* in_sizes, int n_in,
                              void* d_out, int out_size)
{
    const float* x       = (const float*)d_in[0];
    const float* pos_emb = (const float*)d_in[1];
    const float* w_qkv   = (const float*)d_in[2];
    const float* scale   = (const float*)d_in[3];
    const float* w_out   = (const float*)d_in[4];
    const float* b_out   = (const float*)d_in[5];
    float* out = (float*)d_out;

    __half *ah, *al, *wqh, *woh, *qh, *ql, *kh, *vh;
    cudaGetSymbolAddress((void**)&ah,  g_Ah);
    cudaGetSymbolAddress((void**)&al,  g_Al);
    cudaGetSymbolAddress((void**)&wqh, g_Wqh);
    cudaGetSymbolAddress((void**)&woh, g_Woh);
    cudaGetSymbolAddress((void**)&qh,  g_qh);
    cudaGetSymbolAddress((void**)&ql,  g_ql);
    cudaGetSymbolAddress((void**)&kh,  g_kh);
    cudaGetSymbolAddress((void**)&vh,  g_vh);

    cudaFuncSetAttribute(attention_mma3,
                         cudaFuncAttributeMaxDynamicSharedMemorySize,
                         ATT3_SMEM);
    cudaFuncSetAttribute(gemm_f16p,
                         cudaFuncAttributeMaxDynamicSharedMemorySize,
                         GEMM_SMEM);
    cudaFuncSetAttribute(gemm_qkv_rot,
                         cudaFuncAttributeMaxDynamicSharedMemorySize,
                         GEMM_SMEM);

    // 0) weights: transpose + fp16 quantize [N,K]
    transpose_half_kernel<<<dim3(QKVCOLS / 32, DIM / 32), dim3(32, 8)>>>(
        w_qkv, wqh, DIM, QKVCOLS);
    transpose_half_kernel<<<dim3(DIM / 32, INNER / 32), dim3(32, 8)>>>(
        w_out, woh, INNER, DIM);

    // 1) x -> fp16 hi/lo
    {
        int n4 = MROWS * DIM / 4;
        split_kernel<<<(n4 + 255) / 256, 256>>>(x, ah, al, n4);
    }

    // 2) qkv GEMM with fused rotary+scale+scatter+split
    gemm_qkv_rot<<<dim3(QKVCOLS / 128, MROWS / 64), 256, GEMM_SMEM>>>(
        ah, al, wqh, pos_emb, scale, qh, ql, kh, vh);

    // 3) attention (fp16 tensor-core, writes split output for out-proj)
    attention_mma3<<<BATCH * HEADS, 224, ATT3_SMEM>>>(
        qh, ql, kh, vh, ah, al);

    // 4) out = att @ w_out + b_out
    gemm_f16p<<<dim3(DIM / 128, MROWS / 64), 256, GEMM_SMEM>>>(
        ah, al, woh, b_out, out, MROWS, DIM, INNER);
}

// round 17
// speedup vs baseline: 4.5330x; 1.0022x over previous
#include <cuda_runtime.h>
#include <cuda_fp16.h>
#include <cstdint>
#include <math.h>

// ---------------- problem constants ----------------
constexpr int BATCH   = 64;
constexpr int NTOK    = 197;
constexpr int DIM     = 768;
constexpr int HEADS   = 12;
constexpr int DHEAD   = 64;
constexpr int INNER   = HEADS * DHEAD;      // 768
constexpr int MROWS   = BATCH * NTOK;       // 12608 = 64 * 197
constexpr int QKVCOLS = 3 * INNER;          // 2304
constexpr int BHN     = BATCH * HEADS * NTOK * DHEAD;
constexpr float MASK_FILL = -987654321.0f;

// ---------------- scratch (device globals) ----------------
__device__ __align__(16) __half g_Ah[(size_t)MROWS * DIM];
__device__ __align__(16) __half g_Al[(size_t)MROWS * DIM];
__device__ __align__(16) __half g_Wqh[(size_t)QKVCOLS * DIM];
__device__ __align__(16) __half g_Woh[(size_t)DIM * INNER];
__device__ __align__(16) __half g_qh[BHN];
__device__ __align__(16) __half g_ql[BHN];
__device__ __align__(16) __half g_kh[BHN];
__device__ __align__(16) __half g_vh[BHN];

// ---------------- helpers ----------------
__device__ __forceinline__ void split2h(float x, float y,
                                        uint32_t& hi, uint32_t& lo) {
    __half hx = __float2half_rn(x);
    __half hy = __float2half_rn(y);
    __half2 hp;
    hp.x = hx; hp.y = hy;
    hi = *reinterpret_cast<uint32_t*>(&hp);
    __half2 lp;
    lp.x = __float2half_rn(x - __half2float(hx));
    lp.y = __float2half_rn(y - __half2float(hy));
    lo = *reinterpret_cast<uint32_t*>(&lp);
}

__device__ __forceinline__ uint32_t pack2h(float x, float y) {
    __half2 hp;
    hp.x = __float2half_rn(x);
    hp.y = __float2half_rn(y);
    return *reinterpret_cast<uint32_t*>(&hp);
}

__device__ __forceinline__ void mma16816(float* c, const uint32_t* a,
                                         const uint32_t* b) {
    asm volatile(
        "mma.sync.aligned.m16n8k16.row.col.f32.f16.f16.f32 "
        "{%0,%1,%2,%3}, {%4,%5,%6,%7}, {%8,%9}, {%0,%1,%2,%3};"
        : "+f"(c[0]), "+f"(c[1]), "+f"(c[2]), "+f"(c[3])
        : "r"(a[0]), "r"(a[1]), "r"(a[2]), "r"(a[3]),
          "r"(b[0]), "r"(b[1]));
}

__device__ __forceinline__ void ldm_x4(uint32_t* r, uint32_t addr) {
    asm volatile("ldmatrix.sync.aligned.m8n8.x4.shared.b16 {%0,%1,%2,%3}, [%4];"
        : "=r"(r[0]), "=r"(r[1]), "=r"(r[2]), "=r"(r[3]) : "r"(addr));
}

__device__ __forceinline__ void ldm_x4_t(uint32_t* r, uint32_t addr) {
    asm volatile("ldmatrix.sync.aligned.m8n8.x4.trans.shared.b16 {%0,%1,%2,%3}, [%4];"
        : "=r"(r[0]), "=r"(r[1]), "=r"(r[2]), "=r"(r[3]) : "r"(addr));
}

__device__ __forceinline__ uint32_t smem_u32(const void* p) {
    uint32_t a;
    asm("{ .reg .u64 t; cvta.to.shared.u64 t, %1; cvt.u32.u64 %0, t; }"
        : "=r"(a) : "l"(p));
    return a;
}

__device__ __forceinline__ void cpa16(uint32_t dst, const void* src) {
    asm volatile("cp.async.cg.shared.global [%0], [%1], 16;"
        :: "r"(dst), "l"(src));
}

__device__ __forceinline__ void cpa16z(uint32_t dst, const void* src, int vb) {
    asm volatile("cp.async.cg.shared.global [%0], [%1], 16, %2;"
        :: "r"(dst), "l"(src), "r"(vb));
}

// ---------------- pre-split kernels ----------------
__global__ __launch_bounds__(256) void split_kernel(
    const float* __restrict__ src, __half* __restrict__ hi,
    __half* __restrict__ lo, int n4)
{
    int i = blockIdx.x * blockDim.x + threadIdx.x;
    if (i >= n4) return;
    float4 v = ((const float4*)src)[i];
    uint32_t h0, l0, h1, l1;
    split2h(v.x, v.y, h0, l0);
    split2h(v.z, v.w, h1, l1);
    ((uint2*)hi)[i] = make_uint2(h0, h1);
    ((uint2*)lo)[i] = make_uint2(l0, l1);
}

__global__ void transpose_half_kernel(
    const float* __restrict__ src, __half* __restrict__ dhi, int R, int C)
{
    __shared__ float t[32][33];
    int c0 = blockIdx.x * 32, r0 = blockIdx.y * 32;
    int x = threadIdx.x, y = threadIdx.y;   // (32, 8)
    #pragma unroll
    for (int i = 0; i < 32; i += 8)
        t[y + i][x] = src[(size_t)(r0 + y + i) * C + c0 + x];
    __syncthreads();
    #pragma unroll
    for (int i = 0; i < 32; i += 8)
        dhi[(size_t)(c0 + y + i) * R + r0 + x] = __float2half_rn(t[x][y + i]);
}

// ---------------- shared GEMM mainloop: CTA 64x256, warp 32x64 ----------------
// stage: Ah 8K | Al 8K | Bh 32K = 48 KB; 2 stages = 96 KB -> 2 CTAs/SM.
constexpr int GSTAGE    = 49152;
constexpr int GEMM_SMEM = 2 * GSTAGE;    // 98304

struct GemmCtx {
    int tid, lane, wid, g, tig, wm, wn, mBase, nBase;
};

__device__ __forceinline__ GemmCtx make_ctx() {
    GemmCtx cx;
    cx.tid  = threadIdx.x;
    cx.lane = cx.tid & 31;
    cx.wid  = cx.tid >> 5;
    cx.g    = cx.lane >> 2;
    cx.tig  = cx.lane & 3;
    cx.wm   = cx.wid & 1;       // 2 m-warps
    cx.wn   = cx.wid >> 1;      // 4 n-warps
    cx.mBase = blockIdx.y * 64;
    cx.nBase = blockIdx.x * 256;
    return cx;
}

// acc[i][jn][r]: i = m-frag (2 x 16 rows), jn = 8-col group (8), r = frag reg
__device__ __forceinline__ void gemm_mainloop(
    const __half* __restrict__ Ah, const __half* __restrict__ Al,
    const __half* __restrict__ Bh, int K, const GemmCtx& cx,
    uint32_t sb, float acc[2][8][4])
{
    const int KC = K >> 6;
    const int aRow = cx.lane & 15;
    const int aC   = cx.lane >> 4;
    const int bRow = (cx.lane & 7) + ((cx.lane & 16) >> 1);
    const int bC   = (cx.lane >> 3) & 1;

    #pragma unroll
    for (int i = 0; i < 2; i++)
        #pragma unroll
        for (int j = 0; j < 8; j++)
            #pragma unroll
            for (int r = 0; r < 4; r++) acc[i][j][r] = 0.f;

    auto stage_load = [&](int kc, int s) {
        const uint32_t st = sb + s * GSTAGE;
        #pragma unroll
        for (int p = 0; p < 2; p++) {       // A: 64 rows x 8 chunks (hi+lo)
            int idx = cx.tid + p * 256;
            int r = idx >> 3, c = idx & 7;
            uint32_t phys = (uint32_t)(r * 128 + ((c ^ (r & 7)) << 4));
            size_t go = (size_t)(cx.mBase + r) * K + kc * 64 + c * 8;
            cpa16(st + phys,        Ah + go);
            cpa16(st + 8192 + phys, Al + go);
        }
        #pragma unroll
        for (int p = 0; p < 8; p++) {       // B: 256 rows x 8 chunks
            int idx = cx.tid + p * 256;
            int r = idx >> 3, c = idx & 7;
            uint32_t phys = (uint32_t)(r * 128 + ((c ^ (r & 7)) << 4));
            size_t go = (size_t)(cx.nBase + r) * K + kc * 64 + c * 8;
            cpa16(st + 16384 + phys, Bh + go);
        }
    };

    stage_load(0, 0);
    asm volatile("cp.async.commit_group;" ::: "memory");
    if (KC > 1) {
        stage_load(1, 1);
        asm volatile("cp.async.commit_group;" ::: "memory");
    }

    for (int kc = 0; kc < KC; kc++) {
        const int s = kc & 1;
        if (kc == KC - 1)
            asm volatile("cp.async.wait_group 0;" ::: "memory");
        else
            asm volatile("cp.async.wait_group 1;" ::: "memory");
        __syncthreads();

        const uint32_t stA  = sb + s * GSTAGE;
        const uint32_t stAl = stA + 8192;
        const uint32_t stB  = stA + 16384;

        #pragma unroll
        for (int kk = 0; kk < 4; kk++) {
            uint32_t fah[2][4], fal[2][4], fbh[4][4];
            #pragma unroll
            for (int i = 0; i < 2; i++) {
                int row = cx.wm * 32 + i * 16 + aRow;
                int c16 = kk * 2 + aC;
                uint32_t phys = (uint32_t)(row * 128 + ((c16 ^ (row & 7)) << 4));
                ldm_x4(fah[i], stA  + phys);
                ldm_x4(fal[i], stAl + phys);
            }
            #pragma unroll
            for (int j = 0; j < 4; j++) {
                int row = cx.wn * 64 + j * 16 + bRow;
                int c16 = kk * 2 + bC;
                uint32_t phys = (uint32_t)(row * 128 + ((c16 ^ (row & 7)) << 4));
                ldm_x4(fbh[j], stB + phys);
            }
            #pragma unroll
            for (int i = 0; i < 2; i++)
                #pragma unroll
                for (int j = 0; j < 4; j++)
                    #pragma unroll
                    for (int jj = 0; jj < 2; jj++) {
                        float* a = acc[i][j * 2 + jj];
                        mma16816(a, fah[i], fbh[j] + jj * 2);
                        mma16816(a, fal[i], fbh[j] + jj * 2);
                    }
        }
        __syncthreads();

        if (kc + 2 < KC) {
            stage_load(kc + 2, s);
            asm volatile("cp.async.commit_group;" ::: "memory");
        }
    }
}

// ---------------- qkv GEMM with fused rotary+scale+scatter+split --------
__global__ __launch_bounds__(256) void gemm_qkv_rot(
    const __half* __restrict__ Ah, const __half* __restrict__ Al,
    const __half* __restrict__ Bh,
    const float* __restrict__ pos_emb, const float* __restrict__ scale,
    __half* __restrict__ qh, __half* __restrict__ ql,
    __half* __restrict__ kh, __half* __restrict__ vh)
{
    extern __shared__ uint8_t dynsm[];
    const uint32_t sb = smem_u32(dynsm);
    GemmCtx cx = make_ctx();
    float acc[2][8][4];
    gemm_mainloop(Ah, Al, Bh, DIM, cx, sb, acc);

    // fused epilogue: rotary + scale + scatter + fp16 split
    #pragma unroll
    for (int i = 0; i < 2; i++) {
        int gr0 = cx.mBase + cx.wm * 32 + i * 16 + cx.g;
        #pragma unroll
        for (int jn = 0; jn < 8; jn++) {
            int col = cx.nBase + cx.wn * 64 + jn * 8 + 2 * cx.tig;
            int sec = col / INNER;             // 0=q 1=k 2=v
            int cc  = col - sec * INNER;
            int h   = cc >> 6;
            int t   = (cc & 63) >> 1;
            #pragma unroll
            for (int rr = 0; rr < 2; rr++) {
                int m  = gr0 + rr * 8;
                int bb = m / NTOK;
                int ib = m - bb * NTOK;
                float v0 = acc[i][jn][rr * 2];
                float v1 = acc[i][jn][rr * 2 + 1];
                size_t dst = (((size_t)(bb * HEADS + h)) * NTOK + ib) * DHEAD
                             + 2 * t;
                if (sec == 2) {
                    *(uint32_t*)(vh + dst) = pack2h(v0, v1);
                } else {
                    float sn = pos_emb[ib * DHEAD + t];
                    float cs = pos_emb[ib * DHEAD + 32 + t];
                    float r0 = v0 * cs - v1 * sn;
                    float r1 = v1 * cs + v0 * sn;
                    if (sec == 0) {
                        float sc = scale[h];
                        uint32_t hi, lo;
                        split2h(r0 * sc, r1 * sc, hi, lo);
                        *(uint32_t*)(qh + dst) = hi;
                        *(uint32_t*)(ql + dst) = lo;
                    } else {
                        *(uint32_t*)(kh + dst) = pack2h(r0, r1);
                    }
                }
            }
        }
    }
}

// ---------------- plain fp16 2-term GEMM (out projection) ----------------
__global__ __launch_bounds__(256) void gemm_f16p(
    const __half* __restrict__ Ah, const __half* __restrict__ Al,
    const __half* __restrict__ Bh,
    const float* __restrict__ bias, float* __restrict__ C,
    int M, int N, int K)
{
    extern __shared__ uint8_t dynsm[];
    const uint32_t sb = smem_u32(dynsm);
    GemmCtx cx = make_ctx();
    float acc[2][8][4];
    gemm_mainloop(Ah, Al, Bh, K, cx, sb, acc);

    #pragma unroll
    for (int i = 0; i < 2; i++) {
        int r0 = cx.mBase + cx.wm * 32 + i * 16 + cx.g;
        #pragma unroll
        for (int jn = 0; jn < 8; jn++) {
            int c = cx.nBase + cx.wn * 64 + jn * 8 + 2 * cx.tig;
            float b0 = bias ? bias[c]     : 0.f;
            float b1 = bias ? bias[c + 1] : 0.f;
            *(float2*)(C + (size_t)r0 * N + c) =
                make_float2(acc[i][jn][0] + b0, acc[i][jn][1] + b1);
            *(float2*)(C + (size_t)(r0 + 8) * N + c) =
                make_float2(acc[i][jn][2] + b0, acc[i][jn][3] + b1);
        }
    }
}

// ---------------- MMA attention v3 (unchanged) ----------------
constexpr int SMQ  = 224 * 128;
constexpr int SMKV = 256 * 128;
constexpr int OFF_QH = 0;
constexpr int OFF_QL = SMQ;
constexpr int OFF_KH = 2 * SMQ;
constexpr int OFF_VH = 2 * SMQ + SMKV;
constexpr int ATT3_SMEM = 2 * SMQ + 2 * SMKV;   // 122880

__device__ __forceinline__ float maskv(float v, int r, int c) {
    if (c == r)     return MASK_FILL;
    if (c >= NTOK)  return -1e30f;
    return v;
}

__global__ __launch_bounds__(224, 1) void attention_mma3(
    const __half* __restrict__ gqh, const __half* __restrict__ gql,
    const __half* __restrict__ gkh, const __half* __restrict__ gvh,
    __half* __restrict__ oh, __half* __restrict__ ol)
{
    extern __shared__ uint8_t dynsm[];
    const uint32_t sb = smem_u32(dynsm);

    const int bh   = blockIdx.x;
    const int b    = bh / HEADS;
    const int h    = bh - b * HEADS;
    const int tid  = threadIdx.x;
    const int w    = tid >> 5;
    const int lane = tid & 31;
    const int g    = lane >> 2;
    const int tig  = lane & 3;
    const size_t base = (size_t)bh * NTOK * DHEAD;

    for (int i = tid; i < 224 * 8; i += 224) {
        int r = i >> 3, c = i & 7;
        uint32_t phys = (uint32_t)(r * 128 + ((c ^ (r & 7)) << 4));
        int vb = (r < NTOK) ? 16 : 0;
        size_t so = base + (size_t)(r < NTOK ? r : 0) * DHEAD + c * 8;
        cpa16z(sb + OFF_QH + phys, gqh + so, vb);
        cpa16z(sb + OFF_QL + phys, gql + so, vb);
    }
    for (int i = tid; i < 256 * 8; i += 224) {
        int r = i >> 3, c = i & 7;
        uint32_t phys = (uint32_t)(r * 128 + ((c ^ (r & 7)) << 4));
        int vb = (r < NTOK) ? 16 : 0;
        size_t so = base + (size_t)(r < NTOK ? r : 0) * DHEAD + c * 8;
        cpa16z(sb + OFF_KH + phys, gkh + so, vb);
        cpa16z(sb + OFF_VH + phys, gvh + so, vb);
    }
    asm volatile("cp.async.commit_group;" ::: "memory");
    asm volatile("cp.async.wait_group 0;" ::: "memory");
    __syncthreads();

    const int qRO = (lane & 7) + ((lane & 8)  ? 8 : 0);
    const int qC  = (lane & 16) ? 1 : 0;
    const int kRO = (lane & 7) + ((lane & 16) ? 8 : 0);
    const int kC  = (lane & 8)  ? 1 : 0;
    const int i0  = w * 32;

    float out[2][8][4];
    #pragma unroll
    for (int it = 0; it < 2; it++)
        #pragma unroll
        for (int jn = 0; jn < 8; jn++)
            #pragma unroll
            for (int r = 0; r < 4; r++) out[it][jn][r] = 0.f;

    float mrow[2][2] = {{-INFINITY, -INFINITY}, {-INFINITY, -INFINITY}};
    float rsum[2][2] = {{0.f, 0.f}, {0.f, 0.f}};

    for (int c = 0; c < 4; c++) {
        const int jc = c * 64;
        float s[2][8][4];
        #pragma unroll
        for (int it = 0; it < 2; it++)
            #pragma unroll
            for (int jn = 0; jn < 8; jn++)
                #pragma unroll
                for (int r = 0; r < 4; r++) s[it][jn][r] = 0.f;

        #pragma unroll
        for (int kk = 0; kk < 4; kk++) {
            uint32_t qh[2][4], ql[2][4];
            #pragma unroll
            for (int it = 0; it < 2; it++) {
                int row = i0 + it * 16 + qRO;
                int c16 = kk * 2 + qC;
                uint32_t phys = (uint32_t)(row * 128 + ((c16 ^ (row & 7)) << 4));
                ldm_x4(qh[it], sb + OFF_QH + phys);
                ldm_x4(ql[it], sb + OFF_QL + phys);
            }
            #pragma unroll
            for (int np = 0; np < 4; np++) {
                uint32_t khf[4];
                int row = jc + np * 16 + kRO;
                int c16 = kk * 2 + kC;
                uint32_t phys = (uint32_t)(row * 128 + ((c16 ^ (row & 7)) << 4));
                ldm_x4(khf, sb + OFF_KH + phys);
                #pragma unroll
                for (int it = 0; it < 2; it++) {
                    mma16816(s[it][2 * np],     qh[it], khf);
                    mma16816(s[it][2 * np],     ql[it], khf);
                    mma16816(s[it][2 * np + 1], qh[it], khf + 2);
                    mma16816(s[it][2 * np + 1], ql[it], khf + 2);
                }
            }
        }

        float cm[2][2] = {{-INFINITY, -INFINITY}, {-INFINITY, -INFINITY}};
        #pragma unroll
        for (int it = 0; it < 2; it++) {
            int r0 = i0 + it * 16 + g;
            int r1 = r0 + 8;
            #pragma unroll
            for (int jn = 0; jn < 8; jn++) {
                int cb = jc + jn * 8 + 2 * tig;
                float* sv = s[it][jn];
                sv[0] = maskv(sv[0], r0, cb);
                sv[1] = maskv(sv[1], r0, cb + 1);
                sv[2] = maskv(sv[2], r1, cb);
                sv[3] = maskv(sv[3], r1, cb + 1);
                cm[it][0] = fmaxf(cm[it][0], fmaxf(sv[0], sv[1]));
                cm[it][1] = fmaxf(cm[it][1], fmaxf(sv[2], sv[3]));
            }
        }
        #pragma unroll
        for (int it = 0; it < 2; it++)
            #pragma unroll
            for (int hf = 0; hf < 2; hf++) {
                float v = cm[it][hf];
                v = fmaxf(v, __shfl_xor_sync(0xffffffffu, v, 1));
                v = fmaxf(v, __shfl_xor_sync(0xffffffffu, v, 2));
                float mnew = fmaxf(mrow[it][hf], v);
                float sc = __expf(mrow[it][hf] - mnew);
                mrow[it][hf] = mnew;
                rsum[it][hf] *= sc;
                #pragma unroll
                for (int jn = 0; jn < 8; jn++) {
                    out[it][jn][hf * 2]     *= sc;
                    out[it][jn][hf * 2 + 1] *= sc;
                }
            }
        #pragma unroll
        for (int it = 0; it < 2; it++) {
            float ls0 = 0.f, ls1 = 0.f;
            #pragma unroll
            for (int jn = 0; jn < 8; jn++) {
                float* sv = s[it][jn];
                sv[0] = __expf(sv[0] - mrow[it][0]);
                sv[1] = __expf(sv[1] - mrow[it][0]);
                sv[2] = __expf(sv[2] - mrow[it][1]);
                sv[3] = __expf(sv[3] - mrow[it][1]);
                ls0 += sv[0] + sv[1];
                ls1 += sv[2] + sv[3];
            }
            rsum[it][0] += ls0;
            rsum[it][1] += ls1;
        }

        #pragma unroll
        for (int kk = 0; kk < 4; kk++) {
            uint32_t pfh[2][4], pfl[2][4];
            #pragma unroll
            for (int it = 0; it < 2; it++) {
                split2h(s[it][2 * kk][0],     s[it][2 * kk][1],
                        pfh[it][0], pfl[it][0]);
                split2h(s[it][2 * kk][2],     s[it][2 * kk][3],
                        pfh[it][1], pfl[it][1]);
                split2h(s[it][2 * kk + 1][0], s[it][2 * kk + 1][1],
                        pfh[it][2], pfl[it][2]);
                split2h(s[it][2 * kk + 1][2], s[it][2 * kk + 1][3],
                        pfh[it][3], pfl[it][3]);
            }
            #pragma unroll
            for (int np = 0; np < 4; np++) {
                uint32_t vhf[4];
                int row = jc + kk * 16 + qRO;
                int c16 = np * 2 + qC;
                uint32_t phys = (uint32_t)(row * 128 + ((c16 ^ (row & 7)) << 4));
                ldm_x4_t(vhf, sb + OFF_VH + phys);
                #pragma unroll
                for (int it = 0; it < 2; it++) {
                    mma16816(out[it][2 * np],     pfh[it], vhf);
                    mma16816(out[it][2 * np],     pfl[it], vhf);
                    mma16816(out[it][2 * np + 1], pfh[it], vhf + 2);
                    mma16816(out[it][2 * np + 1], pfl[it], vhf + 2);
                }
            }
        }
    }

    #pragma unroll
    for (int it = 0; it < 2; it++) {
        float s0 = rsum[it][0];
        s0 += __shfl_xor_sync(0xffffffffu, s0, 1);
        s0 += __shfl_xor_sync(0xffffffffu, s0, 2);
        float s1 = rsum[it][1];
        s1 += __shfl_xor_sync(0xffffffffu, s1, 1);
        s1 += __shfl_xor_sync(0xffffffffu, s1, 2);
        float inv0 = 1.f / s0, inv1 = 1.f / s1;
        int r0 = i0 + it * 16 + g, r1 = r0 + 8;
        #pragma unroll
        for (int jn = 0; jn < 8; jn++) {
            int d = jn * 8 + 2 * tig;
            uint32_t hi, lo;
            if (r0 < NTOK) {
                size_t e = (size_t)(b * NTOK + r0) * INNER + h * DHEAD + d;
                split2h(out[it][jn][0] * inv0, out[it][jn][1] * inv0, hi, lo);
                *(uint32_t*)(oh + e) = hi;
                *(uint32_t*)(ol + e) = lo;
            }
            if (r1 < NTOK) {
                size_t e = (size_t)(b * NTOK + r1) * INNER + h * DHEAD + d;
                split2h(out[it][jn][2] * inv1, out[it][jn][3] * inv1, hi, lo);
                *(uint32_t*)(oh + e) = hi;
                *(uint32_t*)(ol + e) = lo;
            }
        }
    }
}

// ---------------- launch ----------------
extern "C" void kernel_launch(void* const* d_in, const int* in_sizes, int n_in,
                              void* d_out, int out_size)
{
    const float* x       = (const float*)d_in[0];
    const float* pos_emb = (const float*)d_in[1];
    const float* w_qkv   = (const float*)d_in[2];
    const float* scale   = (const float*)d_in[3];
    const float* w_out   = (const float*)d_in[4];
    const float* b_out   = (const float*)d_in[5];
    float* out = (float*)d_out;

    __half *ah, *al, *wqh, *woh, *qh, *ql, *kh, *vh;
    cudaGetSymbolAddress((void**)&ah,  g_Ah);
    cudaGetSymbolAddress((void**)&al,  g_Al);
    cudaGetSymbolAddress((void**)&wqh, g_Wqh);
    cudaGetSymbolAddress((void**)&woh, g_Woh);
    cudaGetSymbolAddress((void**)&qh,  g_qh);
    cudaGetSymbolAddress((void**)&ql,  g_ql);
    cudaGetSymbolAddress((void**)&kh,  g_kh);
    cudaGetSymbolAddress((void**)&vh,  g_vh);

    cudaFuncSetAttribute(attention_mma3,
                         cudaFuncAttributeMaxDynamicSharedMemorySize,
                         ATT3_SMEM);
    cudaFuncSetAttribute(gemm_f16p,
                         cudaFuncAttributeMaxDynamicSharedMemorySize,
                         GEMM_SMEM);
    cudaFuncSetAttribute(gemm_qkv_rot,
                         cudaFuncAttributeMaxDynamicSharedMemorySize,
                         GEMM_SMEM);

    // 0) weights: transpose + fp16 quantize [N,K]
    transpose_half_kernel<<<dim3(QKVCOLS / 32, DIM / 32), dim3(32, 8)>>>(
        w_qkv, wqh, DIM, QKVCOLS);
    transpose_half_kernel<<<dim3(DIM / 32, INNER / 32), dim3(32, 8)>>>(
        w_out, woh, INNER, DIM);

    // 1) x -> fp16 hi/lo
    {
        int n4 = MROWS * DIM / 4;
        split_kernel<<<(n4 + 255) / 256, 256>>>(x, ah, al, n4);
    }

    // 2) qkv GEMM with fused rotary+scale+scatter+split (CTA 64x256)
    gemm_qkv_rot<<<dim3(QKVCOLS / 256, MROWS / 64), 256, GEMM_SMEM>>>(
        ah, al, wqh, pos_emb, scale, qh, ql, kh, vh);

    // 3) attention (fp16 tensor-core, writes split output for out-proj)
    attention_mma3<<<BATCH * HEADS, 224, ATT3_SMEM>>>(
        qh, ql, kh, vh, ah, al);

    // 4) out = att @ w_out + b_out (CTA 64x256)
    gemm_f16p<<<dim3(DIM / 256, MROWS / 64), 256, GEMM_SMEM>>>(
        ah, al, woh, b_out, out, MROWS, DIM, INNER);
}